// round 5
// baseline (speedup 1.0000x reference)
#include <cuda_runtime.h>
#include <cstdint>

// ============================================================================
// Quantized VGG forward (batch 512) — integer-exact level propagation.
// Activations/weights flow as integer quant levels (float-encoded). Conv GEMMs
// are exact integer sums in fp32 FMA (|S| < 2^24), so quant decisions are
// ideal and order-independent. All value-producing divisions use __fdiv_rn
// (correctly rounded even under --use_fast_math).
// ============================================================================

#define BATCH 512
#define NLAYERS 13

#define ACT_ELEMS (512*64*32*32)
#define WQ_ELEMS 14710464

__device__ float  g_actA[ACT_ELEMS];
__device__ float  g_actB[ACT_ELEMS];
__device__ float  g_wq[WQ_ELEMS];          // integer weight levels m_w, transposed [K][Cout]
__device__ double g_partial[NLAYERS * 256];
__device__ float  g_scale[NLAYERS * 2];    // per layer: {alpha_w, s_w = 7/alpha_w}

// ----------------------------------------------------------------------------
// Weight scale: fp64-exact abs-mean -> fp32 (correctly rounded), fp32 alpha/s
// ----------------------------------------------------------------------------
__global__ void absum_kernel(const float* __restrict__ w, int n, double* __restrict__ partial) {
    __shared__ double s[256];
    double acc = 0.0;
    for (int i = blockIdx.x * 256 + threadIdx.x; i < n; i += 256 * 256)
        acc += (double)fabsf(w[i]);
    s[threadIdx.x] = acc;
    __syncthreads();
    for (int o = 128; o > 0; o >>= 1) {
        if (threadIdx.x < o) s[threadIdx.x] += s[threadIdx.x + o];
        __syncthreads();
    }
    if (threadIdx.x == 0) partial[blockIdx.x] = s[0];
}

__global__ void finalize_kernel(const double* __restrict__ partial, int n, float* __restrict__ scale_out) {
    __shared__ double s[256];
    s[threadIdx.x] = partial[threadIdx.x];
    __syncthreads();
    for (int o = 128; o > 0; o >>= 1) {
        if (threadIdx.x < o) s[threadIdx.x] += s[threadIdx.x + o];
        __syncthreads();
    }
    if (threadIdx.x == 0) {
        float sum_f = (float)s[0];                      // correctly-rounded fp32 sum
        float mean  = __fdiv_rn(sum_f, (float)n);       // IEEE division
        float alpha = 2.0f * mean;                      // KW = 2.0 (exact mul by 2)
        float sw    = __fdiv_rn(7.0f, alpha);           // IEEE division
        scale_out[0] = alpha;
        scale_out[1] = sw;
    }
}

// Weight -> integer level m_w (reference-exact ops), transposed [K][Cout]
__global__ void quantw_kernel(const float* __restrict__ w, int n, int K, int Cout,
                              const float* __restrict__ scale_p, float* __restrict__ wq_t) {
    int idx = blockIdx.x * blockDim.x + threadIdx.x;
    if (idx >= n) return;
    float alpha = scale_p[0];
    float s     = scale_p[1];
    float v  = w[idx];
    float wc = fminf(fmaxf(v, -alpha), alpha);
    float m  = rintf(wc * s);                  // integer level in [-7,7], half-even
    int mo = idx / K;
    int k  = idx - mo * K;
    wq_t[k * Cout + mo] = m;
}

// ----------------------------------------------------------------------------
// Implicit-GEMM conv, 3x3 pad 1 stride 1, NCHW on integer levels.
// Epilogue: m_out = clamp(rint(S * F), 0, 15), F computed in fp64.
// layer 0: input is raw fp32 x (not levels) -> S has tiny noise; F = 15/(alpha_a*s_w)
// layers >=1: input is integer levels -> S exact; F = scale_a/(s_w*scale_prev)
// ----------------------------------------------------------------------------
__global__ __launch_bounds__(256) void conv_gemm_kernel(
    const float* __restrict__ in, const float* __restrict__ wq_t,
    float* __restrict__ out, int CIN, int COUT, int H,
    const float* __restrict__ alphas, const float* __restrict__ scale_p, int layer)
{
    const int W = H, HW = H * H;
    const int K = CIN * 9;
    const int N = BATCH * HW;

    __shared__ float As[8][128];
    __shared__ float Bs[8][128];

    const int t = threadIdx.x;
    const int bx = blockIdx.x, by = blockIdx.y;

    const int lcol = t & 127;
    const int kl   = t >> 7;
    const int jcol = bx * 128 + lcol;
    const bool jvalid = (jcol < N);
    int n_ = 0, y_ = 0, x_ = 0;
    if (jvalid) {
        n_ = jcol / HW;
        int rem = jcol - n_ * HW;
        y_ = rem / W;
        x_ = rem - y_ * W;
    }
    const float* inbase = in + (size_t)n_ * CIN * HW;

    const int arow = by * 128 + lcol;
    const bool avalid = (arow < COUT);

    float acc[8][8];
    #pragma unroll
    for (int i = 0; i < 8; i++)
        #pragma unroll
        for (int j = 0; j < 8; j++) acc[i][j] = 0.f;

    const int tm0 = (t & 15) * 8;
    const int tn0 = (t >> 4) * 8;
    const int KT = (K + 7) / 8;

    for (int kt = 0; kt < KT; ++kt) {
        const int kbase = kt * 8;
        #pragma unroll
        for (int i = 0; i < 4; i++) {
            int kk = kl + 2 * i;
            int kg = kbase + kk;
            float v = 0.f;
            if (avalid && kg < K) v = wq_t[kg * COUT + arow];
            As[kk][lcol] = v;
        }
        #pragma unroll
        for (int i = 0; i < 4; i++) {
            int kk = kl + 2 * i;
            int kg = kbase + kk;
            float v = 0.f;
            if (jvalid && kg < K) {
                int ci = kg / 9;
                int rs = kg - ci * 9;
                int r = rs / 3;
                int s2 = rs - r * 3;
                int yy = y_ + r - 1;
                int xx = x_ + s2 - 1;
                if (yy >= 0 && yy < H && xx >= 0 && xx < W)
                    v = inbase[ci * HW + yy * W + xx];
            }
            Bs[kk][lcol] = v;
        }
        __syncthreads();

        #pragma unroll
        for (int kk = 0; kk < 8; kk++) {
            float a[8], b[8];
            #pragma unroll
            for (int i = 0; i < 8; i++) a[i] = As[kk][tm0 + i];
            #pragma unroll
            for (int j = 0; j < 8; j++) b[j] = Bs[kk][tn0 + j];
            #pragma unroll
            for (int i = 0; i < 8; i++)
                #pragma unroll
                for (int j = 0; j < 8; j++)
                    acc[i][j] = fmaf(a[i], b[j], acc[i][j]);  // exact for int layers
        }
        __syncthreads();
    }

    // Epilogue: ideal quant decision via fp64 factor
    const float alpha_a  = __ldg(&alphas[layer]);
    const float s_w      = scale_p[2 * layer + 1];
    const double scale_a = 15.0 / (double)alpha_a;
    double scale_prev = 1.0;
    if (layer > 0) {
        float ap = __ldg(&alphas[layer - 1]);
        scale_prev = 15.0 / (double)ap;
    }
    const double F = scale_a / ((double)s_w * scale_prev);

    #pragma unroll
    for (int i = 0; i < 8; i++) {
        int m = by * 128 + tm0 + i;
        if (m >= COUT) continue;
        #pragma unroll
        for (int j = 0; j < 8; j++) {
            int jj = bx * 128 + tn0 + j;
            if (jj >= N) continue;
            int n2 = jj / HW;
            int rem = jj - n2 * HW;
            double td = (double)acc[i][j] * F;          // ~exact preact*scale
            float  tq = (float)rint(td);
            tq = fminf(fmaxf(tq, 0.f), 15.f);           // integer level 0..15
            out[((size_t)n2 * COUT + m) * HW + rem] = tq;
        }
    }
}

// ----------------------------------------------------------------------------
// 2x2 maxpool stride 2, NCHW. If convert!=0, output value = m / scale_last
// (correctly-rounded division), converting levels -> real activations.
// ----------------------------------------------------------------------------
__global__ void pool_kernel(const float* __restrict__ in, float* __restrict__ out,
                            int C, int Hin, int convert, const float* __restrict__ alphas,
                            int layer) {
    int Hout = Hin >> 1;
    int total = BATCH * C * Hout * Hout;
    int idx = blockIdx.x * blockDim.x + threadIdx.x;
    if (idx >= total) return;
    int x = idx % Hout;
    int tmp = idx / Hout;
    int y = tmp % Hout;
    tmp /= Hout;
    int c = tmp % C;
    int n = tmp / C;
    const float* p = in + ((size_t)(n * C + c) * Hin + 2 * y) * Hin + 2 * x;
    float v = fmaxf(fmaxf(p[0], p[1]), fmaxf(p[Hin], p[Hin + 1]));
    if (convert) {
        float sc = __fdiv_rn(15.0f, __ldg(&alphas[layer]));  // = 1.5 exactly for alpha=10
        v = __fdiv_rn(v, sc);                                // reference activation value
    }
    out[idx] = v;
}

// ----------------------------------------------------------------------------
// FC: out = act @ w^T + b, optional relu (no quantizers downstream -> plain fp32)
// ----------------------------------------------------------------------------
__global__ void fc_kernel(const float* __restrict__ act, const float* __restrict__ w,
                          const float* __restrict__ bias, float* __restrict__ out,
                          int M, int N, int K, int dorelu) {
    __shared__ float As[16][16];
    __shared__ float Ws[16][17];
    int row = blockIdx.y * 16 + threadIdx.y;
    int col = blockIdx.x * 16 + threadIdx.x;
    float acc = 0.f;
    for (int kt = 0; kt < K; kt += 16) {
        As[threadIdx.y][threadIdx.x] = (row < M) ? act[row * K + kt + threadIdx.x] : 0.f;
        int wrow = blockIdx.x * 16 + threadIdx.y;
        Ws[threadIdx.y][threadIdx.x] = (wrow < N) ? w[wrow * K + kt + threadIdx.x] : 0.f;
        __syncthreads();
        #pragma unroll
        for (int k = 0; k < 16; k++)
            acc = fmaf(As[threadIdx.y][k], Ws[threadIdx.x][k], acc);
        __syncthreads();
    }
    if (row < M && col < N) {
        acc += bias[col];
        if (dorelu) acc = fmaxf(acc, 0.f);
        out[row * N + col] = acc;
    }
}

// ----------------------------------------------------------------------------
// Host orchestration
// ----------------------------------------------------------------------------
struct LayerCfg { int cin, cout, h; bool pool_after; };
static const LayerCfg g_layers[NLAYERS] = {
    {  3,  64, 32, false},
    { 64,  64, 32, true },
    { 64, 128, 16, false},
    {128, 128, 16, true },
    {128, 256,  8, false},
    {256, 256,  8, false},
    {256, 256,  8, true },
    {256, 512,  4, false},
    {512, 512,  4, false},
    {512, 512,  4, true },
    {512, 512,  2, false},
    {512, 512,  2, false},
    {512, 512,  2, true },
};

extern "C" void kernel_launch(void* const* d_in, const int* in_sizes, int n_in,
                              void* d_out, int out_size) {
    (void)in_sizes; (void)n_in; (void)out_size;

    const float* x      = (const float*)d_in[0];
    const float* convw[NLAYERS];
    for (int i = 0; i < NLAYERS; i++) convw[i] = (const float*)d_in[1 + i];
    const float* alphas = (const float*)d_in[14];
    const float* fc1_w  = (const float*)d_in[15];
    const float* fc1_b  = (const float*)d_in[16];
    const float* fc2_w  = (const float*)d_in[17];
    const float* fc2_b  = (const float*)d_in[18];
    const float* fc3_w  = (const float*)d_in[19];
    const float* fc3_b  = (const float*)d_in[20];

    float *actA, *actB, *wq, *scale;
    double *partial;
    cudaGetSymbolAddress((void**)&actA,    g_actA);
    cudaGetSymbolAddress((void**)&actB,    g_actB);
    cudaGetSymbolAddress((void**)&wq,      g_wq);
    cudaGetSymbolAddress((void**)&partial, g_partial);
    cudaGetSymbolAddress((void**)&scale,   g_scale);

    long woff[NLAYERS];
    long acc_off = 0;
    for (int i = 0; i < NLAYERS; i++) {
        woff[i] = acc_off;
        acc_off += (long)g_layers[i].cout * g_layers[i].cin * 9;
    }

    for (int i = 0; i < NLAYERS; i++) {
        int n = g_layers[i].cout * g_layers[i].cin * 9;
        int K = g_layers[i].cin * 9;
        absum_kernel<<<256, 256>>>(convw[i], n, partial + i * 256);
        finalize_kernel<<<1, 256>>>(partial + i * 256, n, scale + i * 2);
        int grid = (n + 255) / 256;
        quantw_kernel<<<grid, 256>>>(convw[i], n, K, g_layers[i].cout,
                                     scale + i * 2, wq + woff[i]);
    }

    float* buf[2] = {actA, actB};
    const float* src = x;
    int cur = -1;

    for (int i = 0; i < NLAYERS; i++) {
        const LayerCfg& L = g_layers[i];
        int N = BATCH * L.h * L.h;
        int dst = (cur == 0) ? 1 : 0;
        dim3 grid((N + 127) / 128, (L.cout + 127) / 128);
        conv_gemm_kernel<<<grid, 256>>>(src, wq + woff[i], buf[dst],
                                        L.cin, L.cout, L.h, alphas, scale, i);
        cur = dst;
        src = buf[cur];
        if (L.pool_after) {
            int dst2 = 1 - cur;
            int Hout = L.h >> 1;
            int total = BATCH * L.cout * Hout * Hout;
            int convert = (i == NLAYERS - 1) ? 1 : 0;   // final pool: levels -> values
            pool_kernel<<<(total + 255) / 256, 256>>>(src, buf[dst2], L.cout, L.h,
                                                      convert, alphas, i);
            cur = dst2;
            src = buf[cur];
        }
    }

    {
        int dst = 1 - cur;
        dim3 grid1((512 + 15) / 16, (BATCH + 15) / 16);
        fc_kernel<<<grid1, dim3(16, 16)>>>(src, fc1_w, fc1_b, buf[dst], BATCH, 512, 512, 1);
        cur = dst; src = buf[cur];

        dst = 1 - cur;
        fc_kernel<<<grid1, dim3(16, 16)>>>(src, fc2_w, fc2_b, buf[dst], BATCH, 512, 512, 1);
        cur = dst; src = buf[cur];

        dim3 grid3((10 + 15) / 16, (BATCH + 15) / 16);
        fc_kernel<<<grid3, dim3(16, 16)>>>(src, fc3_w, fc3_b, (float*)d_out, BATCH, 10, 512, 0);
    }
}

// round 6
// speedup vs baseline: 3.1601x; 3.1601x over previous
#include <cuda_runtime.h>
#include <cstdint>

// ============================================================================
// Quantized VGG forward (batch 512) — integer levels end-to-end, dp4a convs.
// Acts: u8 NHWC levels (0..15). Weights: s8 levels (-7..7) packed 4/word in
// K-order (r,s | ci). Conv GEMM = int32 dp4a accumulation (exact, any order).
// Epilogue quant decision via fp64 factor (bit-identical to R5's rel_err=0).
// Layer 0 (CIN=3) stays fp32. FC head fp32.
// ============================================================================

#define BATCH 512
#define NLAYERS 13

#define ACT8_ELEMS (512*64*32*32)     // 33.5M u8 max
#define WQ8_WORDS  4000000            // packed int32 words, layers 1-12 (needs 3,676,608)

__device__ uint8_t g_act8A[ACT8_ELEMS];
__device__ uint8_t g_act8B[ACT8_ELEMS];
__device__ float   g_fc0[BATCH * 512];     // FC input values
__device__ float   g_fcA[BATCH * 512];
__device__ float   g_fcB[BATCH * 512];
__device__ float   g_wq0[27 * 64];         // layer0 float levels, transposed [K][Cout]
__device__ int     g_wq8[WQ8_WORDS];       // packed s8 weights, [K4][Cout] per layer
__device__ double  g_partial[NLAYERS * 256];
__device__ float   g_scale[NLAYERS * 2];   // {alpha_w, s_w}

__device__ __forceinline__ int dp4a_su(int a, unsigned b, int c) {
    int d;
    asm("dp4a.s32.u32 %0, %1, %2, %3;" : "=r"(d) : "r"(a), "r"(b), "r"(c));
    return d;
}

// ----------------------------------------------------------------------------
// Weight scale pipeline (unchanged from R5 — produced rel_err 0.0)
// ----------------------------------------------------------------------------
__global__ void absum_kernel(const float* __restrict__ w, int n, double* __restrict__ partial) {
    __shared__ double s[256];
    double acc = 0.0;
    for (int i = blockIdx.x * 256 + threadIdx.x; i < n; i += 256 * 256)
        acc += (double)fabsf(w[i]);
    s[threadIdx.x] = acc;
    __syncthreads();
    for (int o = 128; o > 0; o >>= 1) {
        if (threadIdx.x < o) s[threadIdx.x] += s[threadIdx.x + o];
        __syncthreads();
    }
    if (threadIdx.x == 0) partial[blockIdx.x] = s[0];
}

__global__ void finalize_kernel(const double* __restrict__ partial, int n, float* __restrict__ scale_out) {
    __shared__ double s[256];
    s[threadIdx.x] = partial[threadIdx.x];
    __syncthreads();
    for (int o = 128; o > 0; o >>= 1) {
        if (threadIdx.x < o) s[threadIdx.x] += s[threadIdx.x + o];
        __syncthreads();
    }
    if (threadIdx.x == 0) {
        float sum_f = (float)s[0];
        float mean  = __fdiv_rn(sum_f, (float)n);
        float alpha = 2.0f * mean;
        float sw    = __fdiv_rn(7.0f, alpha);
        scale_out[0] = alpha;
        scale_out[1] = sw;
    }
}

// Layer 0: float levels transposed [K=27][Cout=64]
__global__ void quantw0_kernel(const float* __restrict__ w, int n, int K, int Cout,
                               const float* __restrict__ scale_p, float* __restrict__ wq_t) {
    int idx = blockIdx.x * blockDim.x + threadIdx.x;
    if (idx >= n) return;
    float alpha = scale_p[0];
    float s     = scale_p[1];
    float wc = fminf(fmaxf(w[idx], -alpha), alpha);
    float m  = rintf(wc * s);
    int mo = idx / K;
    int k  = idx - mo * K;
    wq_t[k * Cout + mo] = m;
}

// Layers 1-12: pack 4 s8 levels per int32, K-order k' = (r*3+s)*CIN + ci,
// output word index: k4 * Cout + m
__global__ void quantw_pack_kernel(const float* __restrict__ w, int CIN, int Cout,
                                   const float* __restrict__ scale_p, int* __restrict__ wq8) {
    int K4 = (CIN * 9) >> 2;
    int total = K4 * Cout;
    int idx = blockIdx.x * blockDim.x + threadIdx.x;
    if (idx >= total) return;
    int k4 = idx / Cout;
    int m  = idx - k4 * Cout;
    int cin4 = CIN >> 2;
    int rs = k4 / cin4;
    int ci0 = (k4 - rs * cin4) << 2;
    int r = rs / 3;
    int s2 = rs - r * 3;
    float alpha = scale_p[0];
    float s = scale_p[1];
    unsigned pack = 0;
    #pragma unroll
    for (int t = 0; t < 4; t++) {
        int ci = ci0 + t;
        float v = w[((m * CIN + ci) * 3 + r) * 3 + s2];
        float wc = fminf(fmaxf(v, -alpha), alpha);
        int mi = (int)rintf(wc * s);          // [-7,7]
        pack |= ((unsigned)(mi & 0xFF)) << (8 * t);
    }
    wq8[k4 * Cout + m] = (int)pack;
}

// ----------------------------------------------------------------------------
// Layer 0 conv: fp32 GEMM (K=27), input x NCHW fp32, output u8 NHWC levels.
// ----------------------------------------------------------------------------
__global__ __launch_bounds__(256) void conv0_kernel(
    const float* __restrict__ x, const float* __restrict__ wq_t,
    uint8_t* __restrict__ out,
    const float* __restrict__ alphas, const float* __restrict__ scale_p)
{
    const int CIN = 3, COUT = 64, H = 32, W = 32, HW = 1024;
    const int K = 27;
    const int N = BATCH * HW;

    __shared__ float As[8][128];
    __shared__ float Bs[8][128];

    const int t = threadIdx.x;
    const int bx = blockIdx.x;

    const int lcol = t & 127;
    const int kl   = t >> 7;
    const int jcol = bx * 128 + lcol;
    int n_ = jcol / HW;
    int rem = jcol - n_ * HW;
    int y_ = rem >> 5;
    int x_ = rem & 31;
    const float* inbase = x + (size_t)n_ * CIN * HW;

    const int arow = lcol;       // grid.y == 1, Cout=64
    const bool avalid = (arow < COUT);

    float acc[8][8];
    #pragma unroll
    for (int i = 0; i < 8; i++)
        #pragma unroll
        for (int j = 0; j < 8; j++) acc[i][j] = 0.f;

    const int tm0 = (t & 15) * 8;
    const int tn0 = (t >> 4) * 8;

    for (int kt = 0; kt < 4; ++kt) {
        const int kbase = kt * 8;
        #pragma unroll
        for (int i = 0; i < 4; i++) {
            int kk = kl + 2 * i;
            int kg = kbase + kk;
            float v = 0.f;
            if (avalid && kg < K) v = wq_t[kg * COUT + arow];
            As[kk][lcol] = v;
        }
        #pragma unroll
        for (int i = 0; i < 4; i++) {
            int kk = kl + 2 * i;
            int kg = kbase + kk;
            float v = 0.f;
            if (kg < K) {
                int ci = kg / 9;
                int rs = kg - ci * 9;
                int r = rs / 3;
                int s2 = rs - r * 3;
                int yy = y_ + r - 1;
                int xx = x_ + s2 - 1;
                if (yy >= 0 && yy < H && xx >= 0 && xx < W)
                    v = inbase[ci * HW + yy * W + xx];
            }
            Bs[kk][lcol] = v;
        }
        __syncthreads();
        #pragma unroll
        for (int kk = 0; kk < 8; kk++) {
            float a[8], b[8];
            #pragma unroll
            for (int i = 0; i < 8; i++) a[i] = As[kk][tm0 + i];
            #pragma unroll
            for (int j = 0; j < 8; j++) b[j] = Bs[kk][tn0 + j];
            #pragma unroll
            for (int i = 0; i < 8; i++)
                #pragma unroll
                for (int j = 0; j < 8; j++)
                    acc[i][j] = fmaf(a[i], b[j], acc[i][j]);
        }
        __syncthreads();
    }

    // Epilogue: F = scale_a / s_w (layer 0)
    const float alpha_a = __ldg(&alphas[0]);
    const float s_w     = scale_p[1];
    const double F = (15.0 / (double)alpha_a) / (double)s_w;

    #pragma unroll
    for (int i = 0; i < 8; i++) {
        int m = tm0 + i;
        if (m >= COUT) continue;
        #pragma unroll
        for (int j = 0; j < 8; j++) {
            int jj = bx * 128 + tn0 + j;
            int n2 = jj / HW;
            int rm = jj - n2 * HW;
            int yy = rm >> 5, xx = rm & 31;
            double td = (double)acc[i][j] * F;
            float tq = (float)rint(td);
            tq = fminf(fmaxf(tq, 0.f), 15.f);
            out[(((size_t)n2 * H + yy) * W + xx) * COUT + m] = (uint8_t)tq;
        }
    }
}

// ----------------------------------------------------------------------------
// dp4a conv (layers 1-12): u8 NHWC in -> u8 NHWC out.
// K packed: K4 = CIN*9/4. Tile 128x128, 8 packed-k (=32 real K) per stage.
// ----------------------------------------------------------------------------
__global__ __launch_bounds__(256) void conv_dp4a_kernel(
    const uint8_t* __restrict__ in, const int* __restrict__ wq8,
    uint8_t* __restrict__ out, int CIN, int COUT, int H, int sh,
    const float* __restrict__ alphas, const float* __restrict__ scale_p, int layer)
{
    const int W = H, HW = H * H;
    const int K4 = (CIN * 9) >> 2;
    const int cmask = (1 << sh) - 1;     // CIN/4 - 1

    __shared__ int      As[8][128];
    __shared__ unsigned Bs[8][128];

    const int t = threadIdx.x;
    const int bx = blockIdx.x, by = blockIdx.y;

    const int lcol = t & 127;
    const int kl   = t >> 7;
    const int jcol = bx * 128 + lcol;
    int n_ = jcol / HW;
    int rem = jcol - n_ * HW;
    int y_ = rem / W;
    int x_ = rem - y_ * W;
    const uint8_t* inb = in + (size_t)n_ * HW * CIN;

    const int arow = by * 128 + lcol;
    const bool avalid = (arow < COUT);

    int acc[8][8];
    #pragma unroll
    for (int i = 0; i < 8; i++)
        #pragma unroll
        for (int j = 0; j < 8; j++) acc[i][j] = 0;

    const int tm0 = (t & 15) * 8;
    const int tn0 = (t >> 4) * 8;
    const int KT = K4 >> 3;              // always exact

    for (int kt = 0; kt < KT; ++kt) {
        const int kbase = kt * 8;
        #pragma unroll
        for (int i = 0; i < 4; i++) {
            int kk = kl + 2 * i;
            int kg = kbase + kk;
            int v = 0;
            if (avalid) v = wq8[kg * COUT + arow];
            As[kk][lcol] = v;
        }
        #pragma unroll
        for (int i = 0; i < 4; i++) {
            int kk = kl + 2 * i;
            int kg = kbase + kk;
            int rs = kg >> sh;
            int ci = (kg & cmask) << 2;
            int r = rs / 3;
            int s2 = rs - r * 3;
            int yy = y_ + r - 1;
            int xx = x_ + s2 - 1;
            unsigned v = 0;
            if (yy >= 0 && yy < H && xx >= 0 && xx < W)
                v = *(const unsigned*)(inb + ((size_t)yy * W + xx) * CIN + ci);
            Bs[kk][lcol] = v;
        }
        __syncthreads();

        #pragma unroll
        for (int kk = 0; kk < 8; kk++) {
            int a[8]; unsigned b[8];
            #pragma unroll
            for (int i = 0; i < 8; i++) a[i] = As[kk][tm0 + i];
            #pragma unroll
            for (int j = 0; j < 8; j++) b[j] = Bs[kk][tn0 + j];
            #pragma unroll
            for (int i = 0; i < 8; i++)
                #pragma unroll
                for (int j = 0; j < 8; j++)
                    acc[i][j] = dp4a_su(a[i], b[j], acc[i][j]);
        }
        __syncthreads();
    }

    // Epilogue: F = scale_a / (s_w * scale_prev), fp64 (exact decisions)
    const float alpha_a = __ldg(&alphas[layer]);
    const float s_w     = scale_p[2 * layer + 1];
    const float alpha_p = __ldg(&alphas[layer - 1]);
    const double F = (15.0 / (double)alpha_a) / ((double)s_w * (15.0 / (double)alpha_p));

    #pragma unroll
    for (int i = 0; i < 8; i++) {
        int m = by * 128 + tm0 + i;
        if (m >= COUT) continue;
        #pragma unroll
        for (int j = 0; j < 8; j++) {
            int jj = bx * 128 + tn0 + j;
            int n2 = jj / HW;
            int rm = jj - n2 * HW;
            int yy = rm / W, xx = rm - yy * W;
            double td = (double)acc[i][j] * F;
            float tq = (float)rint(td);
            tq = fminf(fmaxf(tq, 0.f), 15.f);
            out[(((size_t)n2 * H + yy) * W + xx) * COUT + m] = (uint8_t)tq;
        }
    }
}

// ----------------------------------------------------------------------------
// 2x2 maxpool stride 2 on u8 NHWC
// ----------------------------------------------------------------------------
__global__ void pool8_kernel(const uint8_t* __restrict__ in, uint8_t* __restrict__ out,
                             int C, int Hin) {
    int Hout = Hin >> 1;
    int total = BATCH * Hout * Hout * C;
    int idx = blockIdx.x * blockDim.x + threadIdx.x;
    if (idx >= total) return;
    int c = idx % C;
    int tmp = idx / C;
    int x = tmp % Hout;
    tmp /= Hout;
    int y = tmp % Hout;
    int n = tmp / Hout;
    const uint8_t* p = in + (((size_t)n * Hin + 2 * y) * Hin + 2 * x) * C + c;
    size_t rows = (size_t)Hin * C;
    uint8_t v0 = p[0], v1 = p[C], v2 = p[rows], v3 = p[rows + C];
    uint8_t v = v0 > v1 ? v0 : v1;
    uint8_t w = v2 > v3 ? v2 : v3;
    out[idx] = v > w ? v : w;
}

// Final pool: u8 levels (H=2, C=512) -> fp32 values [B][512]
__global__ void pool_final_kernel(const uint8_t* __restrict__ in, float* __restrict__ out,
                                  const float* __restrict__ alphas) {
    int total = BATCH * 512;
    int idx = blockIdx.x * blockDim.x + threadIdx.x;
    if (idx >= total) return;
    int c = idx & 511;
    int n = idx >> 9;
    const uint8_t* p = in + (size_t)n * 4 * 512 + c;
    uint8_t v0 = p[0], v1 = p[512], v2 = p[1024], v3 = p[1536];
    uint8_t v = v0 > v1 ? v0 : v1;
    uint8_t w = v2 > v3 ? v2 : v3;
    uint8_t m = v > w ? v : w;
    float sc = __fdiv_rn(15.0f, __ldg(&alphas[12]));
    out[idx] = __fdiv_rn((float)m, sc);
}

// ----------------------------------------------------------------------------
// FC: out = act @ w^T + b, optional relu
// ----------------------------------------------------------------------------
__global__ void fc_kernel(const float* __restrict__ act, const float* __restrict__ w,
                          const float* __restrict__ bias, float* __restrict__ out,
                          int M, int N, int K, int dorelu) {
    __shared__ float As[16][16];
    __shared__ float Ws[16][17];
    int row = blockIdx.y * 16 + threadIdx.y;
    int col = blockIdx.x * 16 + threadIdx.x;
    float acc = 0.f;
    for (int kt = 0; kt < K; kt += 16) {
        As[threadIdx.y][threadIdx.x] = (row < M) ? act[row * K + kt + threadIdx.x] : 0.f;
        int wrow = blockIdx.x * 16 + threadIdx.y;
        Ws[threadIdx.y][threadIdx.x] = (wrow < N) ? w[wrow * K + kt + threadIdx.x] : 0.f;
        __syncthreads();
        #pragma unroll
        for (int k = 0; k < 16; k++)
            acc = fmaf(As[threadIdx.y][k], Ws[threadIdx.x][k], acc);
        __syncthreads();
    }
    if (row < M && col < N) {
        acc += bias[col];
        if (dorelu) acc = fmaxf(acc, 0.f);
        out[row * N + col] = acc;
    }
}

// ----------------------------------------------------------------------------
// Host orchestration
// ----------------------------------------------------------------------------
struct LayerCfg { int cin, cout, h; bool pool_after; };
static const LayerCfg g_layers[NLAYERS] = {
    {  3,  64, 32, false},
    { 64,  64, 32, true },
    { 64, 128, 16, false},
    {128, 128, 16, true },
    {128, 256,  8, false},
    {256, 256,  8, false},
    {256, 256,  8, true },
    {256, 512,  4, false},
    {512, 512,  4, false},
    {512, 512,  4, true },
    {512, 512,  2, false},
    {512, 512,  2, false},
    {512, 512,  2, true },
};

static int ilog2(int v) { int r = 0; while ((1 << r) < v) r++; return r; }

extern "C" void kernel_launch(void* const* d_in, const int* in_sizes, int n_in,
                              void* d_out, int out_size) {
    (void)in_sizes; (void)n_in; (void)out_size;

    const float* x      = (const float*)d_in[0];
    const float* convw[NLAYERS];
    for (int i = 0; i < NLAYERS; i++) convw[i] = (const float*)d_in[1 + i];
    const float* alphas = (const float*)d_in[14];
    const float* fc1_w  = (const float*)d_in[15];
    const float* fc1_b  = (const float*)d_in[16];
    const float* fc2_w  = (const float*)d_in[17];
    const float* fc2_b  = (const float*)d_in[18];
    const float* fc3_w  = (const float*)d_in[19];
    const float* fc3_b  = (const float*)d_in[20];

    uint8_t *a8A, *a8B;
    float *fc0, *fcA, *fcB, *wq0, *scale;
    int *wq8;
    double *partial;
    cudaGetSymbolAddress((void**)&a8A,     g_act8A);
    cudaGetSymbolAddress((void**)&a8B,     g_act8B);
    cudaGetSymbolAddress((void**)&fc0,     g_fc0);
    cudaGetSymbolAddress((void**)&fcA,     g_fcA);
    cudaGetSymbolAddress((void**)&fcB,     g_fcB);
    cudaGetSymbolAddress((void**)&wq0,     g_wq0);
    cudaGetSymbolAddress((void**)&wq8,     g_wq8);
    cudaGetSymbolAddress((void**)&partial, g_partial);
    cudaGetSymbolAddress((void**)&scale,   g_scale);

    // Packed weight offsets (int32 words) for layers 1..12
    long w8off[NLAYERS];
    long acc_off = 0;
    for (int i = 1; i < NLAYERS; i++) {
        w8off[i] = acc_off;
        acc_off += (long)((g_layers[i].cin * 9) >> 2) * g_layers[i].cout;
    }

    // Scales for all layers
    for (int i = 0; i < NLAYERS; i++) {
        int n = g_layers[i].cout * g_layers[i].cin * 9;
        absum_kernel<<<256, 256>>>(convw[i], n, partial + i * 256);
        finalize_kernel<<<1, 256>>>(partial + i * 256, n, scale + i * 2);
    }
    // Layer 0 float weights
    quantw0_kernel<<<(27 * 64 + 255) / 256, 256>>>(convw[0], 27 * 64, 27, 64, scale, wq0);
    // Layers 1-12 packed weights
    for (int i = 1; i < NLAYERS; i++) {
        int K4 = (g_layers[i].cin * 9) >> 2;
        int total = K4 * g_layers[i].cout;
        quantw_pack_kernel<<<(total + 255) / 256, 256>>>(convw[i], g_layers[i].cin,
                                                         g_layers[i].cout, scale + i * 2,
                                                         wq8 + w8off[i]);
    }

    // Layer 0: fp32 conv -> u8 NHWC into a8A
    {
        int N = BATCH * 32 * 32;
        conv0_kernel<<<dim3(N / 128, 1), 256>>>(x, wq0, a8A, alphas, scale);
    }

    uint8_t* buf[2] = {a8A, a8B};
    int cur = 0;

    for (int i = 1; i < NLAYERS; i++) {
        const LayerCfg& L = g_layers[i];
        int N = BATCH * L.h * L.h;
        int dst = 1 - cur;
        int sh = ilog2(L.cin >> 2);
        dim3 grid(N / 128, (L.cout + 127) / 128);
        conv_dp4a_kernel<<<grid, 256>>>(buf[cur], wq8 + w8off[i], buf[dst],
                                        L.cin, L.cout, L.h, sh, alphas, scale, i);
        cur = dst;
        if (L.pool_after) {
            if (i == NLAYERS - 1) {
                pool_final_kernel<<<(BATCH * 512 + 255) / 256, 256>>>(buf[cur], fc0, alphas);
            } else {
                int dst2 = 1 - cur;
                int Hout = L.h >> 1;
                int total = BATCH * Hout * Hout * L.cout;
                pool8_kernel<<<(total + 255) / 256, 256>>>(buf[cur], buf[dst2], L.cout, L.h);
                cur = dst2;
            }
        }
    }

    // FC head
    {
        dim3 grid1((512 + 15) / 16, (BATCH + 15) / 16);
        fc_kernel<<<grid1, dim3(16, 16)>>>(fc0, fc1_w, fc1_b, fcA, BATCH, 512, 512, 1);
        fc_kernel<<<grid1, dim3(16, 16)>>>(fcA, fc2_w, fc2_b, fcB, BATCH, 512, 512, 1);
        dim3 grid3(1, (BATCH + 15) / 16);
        fc_kernel<<<grid3, dim3(16, 16)>>>(fcB, fc3_w, fc3_b, (float*)d_out, BATCH, 10, 512, 0);
    }
}

// round 8
// speedup vs baseline: 5.6021x; 1.7728x over previous
#include <cuda_runtime.h>
#include <cstdint>

// ============================================================================
// Quantized VGG forward (batch 512) — integer levels end-to-end.
// Convs 1-12: IMMA mma.sync m16n8k32 (s8 weights x u8 acts -> s32, exact).
// Acts: u8 NHWC levels (0..15). Weights: s8 levels (-7..7) packed 4/word,
// K-order (r,s | ci), layout [K4][Cout]. Epilogue quant via fp64 factor
// (bit-exact decisions -> rel_err 0.0). Layer 0 (CIN=3) fp32. FC head fp32.
// (Resubmission of R7 — infra failure, kernel never executed.)
// ============================================================================

#define BATCH 512
#define NLAYERS 13

#define ACT8_ELEMS (512*64*32*32)
#define WQ8_WORDS  4000000

__device__ uint8_t g_act8A[ACT8_ELEMS];
__device__ uint8_t g_act8B[ACT8_ELEMS];
__device__ float   g_fc0[BATCH * 512];
__device__ float   g_fcA[BATCH * 512];
__device__ float   g_fcB[BATCH * 512];
__device__ float   g_wq0[27 * 64];
__device__ int     g_wq8[WQ8_WORDS];
__device__ double  g_partial[NLAYERS * 256];
__device__ float   g_scale[NLAYERS * 2];

// ----------------------------------------------------------------------------
// Weight scale pipeline (unchanged — rel_err 0.0 verified)
// ----------------------------------------------------------------------------
__global__ void absum_kernel(const float* __restrict__ w, int n, double* __restrict__ partial) {
    __shared__ double s[256];
    double acc = 0.0;
    for (int i = blockIdx.x * 256 + threadIdx.x; i < n; i += 256 * 256)
        acc += (double)fabsf(w[i]);
    s[threadIdx.x] = acc;
    __syncthreads();
    for (int o = 128; o > 0; o >>= 1) {
        if (threadIdx.x < o) s[threadIdx.x] += s[threadIdx.x + o];
        __syncthreads();
    }
    if (threadIdx.x == 0) partial[blockIdx.x] = s[0];
}

__global__ void finalize_kernel(const double* __restrict__ partial, int n, float* __restrict__ scale_out) {
    __shared__ double s[256];
    s[threadIdx.x] = partial[threadIdx.x];
    __syncthreads();
    for (int o = 128; o > 0; o >>= 1) {
        if (threadIdx.x < o) s[threadIdx.x] += s[threadIdx.x + o];
        __syncthreads();
    }
    if (threadIdx.x == 0) {
        float sum_f = (float)s[0];
        float mean  = __fdiv_rn(sum_f, (float)n);
        float alpha = 2.0f * mean;
        float sw    = __fdiv_rn(7.0f, alpha);
        scale_out[0] = alpha;
        scale_out[1] = sw;
    }
}

__global__ void quantw0_kernel(const float* __restrict__ w, int n, int K, int Cout,
                               const float* __restrict__ scale_p, float* __restrict__ wq_t) {
    int idx = blockIdx.x * blockDim.x + threadIdx.x;
    if (idx >= n) return;
    float alpha = scale_p[0];
    float s     = scale_p[1];
    float wc = fminf(fmaxf(w[idx], -alpha), alpha);
    float m  = rintf(wc * s);
    int mo = idx / K;
    int k  = idx - mo * K;
    wq_t[k * Cout + mo] = m;
}

__global__ void quantw_pack_kernel(const float* __restrict__ w, int CIN, int Cout,
                                   const float* __restrict__ scale_p, int* __restrict__ wq8) {
    int K4 = (CIN * 9) >> 2;
    int total = K4 * Cout;
    int idx = blockIdx.x * blockDim.x + threadIdx.x;
    if (idx >= total) return;
    int k4 = idx / Cout;
    int m  = idx - k4 * Cout;
    int cin4 = CIN >> 2;
    int rs = k4 / cin4;
    int ci0 = (k4 - rs * cin4) << 2;
    int r = rs / 3;
    int s2 = rs - r * 3;
    float alpha = scale_p[0];
    float s = scale_p[1];
    unsigned pack = 0;
    #pragma unroll
    for (int t = 0; t < 4; t++) {
        int ci = ci0 + t;
        float v = w[((m * CIN + ci) * 3 + r) * 3 + s2];
        float wc = fminf(fmaxf(v, -alpha), alpha);
        int mi = (int)rintf(wc * s);
        pack |= ((unsigned)(mi & 0xFF)) << (8 * t);
    }
    wq8[k4 * Cout + m] = (int)pack;
}

// ----------------------------------------------------------------------------
// Layer 0 conv: fp32 GEMM (K=27), x NCHW fp32 -> u8 NHWC levels
// ----------------------------------------------------------------------------
__global__ __launch_bounds__(256) void conv0_kernel(
    const float* __restrict__ x, const float* __restrict__ wq_t,
    uint8_t* __restrict__ out,
    const float* __restrict__ alphas, const float* __restrict__ scale_p)
{
    const int CIN = 3, COUT = 64, H = 32, W = 32, HW = 1024;
    const int K = 27;

    __shared__ float As[8][128];
    __shared__ float Bs[8][128];

    const int t = threadIdx.x;
    const int bx = blockIdx.x;

    const int lcol = t & 127;
    const int kl   = t >> 7;
    const int jcol = bx * 128 + lcol;
    int n_ = jcol / HW;
    int rem = jcol - n_ * HW;
    int y_ = rem >> 5;
    int x_ = rem & 31;
    const float* inbase = x + (size_t)n_ * CIN * HW;

    const int arow = lcol;
    const bool avalid = (arow < COUT);

    float acc[8][8];
    #pragma unroll
    for (int i = 0; i < 8; i++)
        #pragma unroll
        for (int j = 0; j < 8; j++) acc[i][j] = 0.f;

    const int tm0 = (t & 15) * 8;
    const int tn0 = (t >> 4) * 8;

    for (int kt = 0; kt < 4; ++kt) {
        const int kbase = kt * 8;
        #pragma unroll
        for (int i = 0; i < 4; i++) {
            int kk = kl + 2 * i;
            int kg = kbase + kk;
            float v = 0.f;
            if (avalid && kg < K) v = wq_t[kg * COUT + arow];
            As[kk][lcol] = v;
        }
        #pragma unroll
        for (int i = 0; i < 4; i++) {
            int kk = kl + 2 * i;
            int kg = kbase + kk;
            float v = 0.f;
            if (kg < K) {
                int ci = kg / 9;
                int rs = kg - ci * 9;
                int r = rs / 3;
                int s2 = rs - r * 3;
                int yy = y_ + r - 1;
                int xx = x_ + s2 - 1;
                if (yy >= 0 && yy < H && xx >= 0 && xx < W)
                    v = inbase[ci * HW + yy * W + xx];
            }
            Bs[kk][lcol] = v;
        }
        __syncthreads();
        #pragma unroll
        for (int kk = 0; kk < 8; kk++) {
            float a[8], b[8];
            #pragma unroll
            for (int i = 0; i < 8; i++) a[i] = As[kk][tm0 + i];
            #pragma unroll
            for (int j = 0; j < 8; j++) b[j] = Bs[kk][tn0 + j];
            #pragma unroll
            for (int i = 0; i < 8; i++)
                #pragma unroll
                for (int j = 0; j < 8; j++)
                    acc[i][j] = fmaf(a[i], b[j], acc[i][j]);
        }
        __syncthreads();
    }

    const float alpha_a = __ldg(&alphas[0]);
    const float s_w     = scale_p[1];
    const double F = (15.0 / (double)alpha_a) / (double)s_w;

    #pragma unroll
    for (int i = 0; i < 8; i++) {
        int m = tm0 + i;
        if (m >= COUT) continue;
        #pragma unroll
        for (int j = 0; j < 8; j++) {
            int jj = bx * 128 + tn0 + j;
            int n2 = jj / HW;
            int rm = jj - n2 * HW;
            int yy = rm >> 5, xx = rm & 31;
            double td = (double)acc[i][j] * F;
            float tq = (float)rint(td);
            tq = fminf(fmaxf(tq, 0.f), 15.f);
            out[(((size_t)n2 * H + yy) * W + xx) * COUT + m] = (uint8_t)tq;
        }
    }
}

// ----------------------------------------------------------------------------
// IMMA conv (layers 1-12): u8 NHWC -> u8 NHWC via mma.sync m16n8k32 s8.u8.s32
// Block tile 128(M=Cout) x 128(N=pixels), 8 warps (2x4), warp tile 64x32.
// ----------------------------------------------------------------------------
__device__ __forceinline__ void imma16832(int* c, const int* a, const unsigned* b) {
    asm volatile(
        "mma.sync.aligned.m16n8k32.row.col.s32.s8.u8.s32 "
        "{%0,%1,%2,%3}, {%4,%5,%6,%7}, {%8,%9}, {%0,%1,%2,%3};"
        : "+r"(c[0]), "+r"(c[1]), "+r"(c[2]), "+r"(c[3])
        : "r"(a[0]), "r"(a[1]), "r"(a[2]), "r"(a[3]),
          "r"(b[0]), "r"(b[1]));
}

__global__ __launch_bounds__(256) void conv_imma_kernel(
    const uint8_t* __restrict__ in, const int* __restrict__ wq8,
    uint8_t* __restrict__ out, int CIN, int COUT, int H, int sh,
    const float* __restrict__ alphas, const float* __restrict__ scale_p, int layer)
{
    const int W = H, HW = H * H;
    const int K4 = (CIN * 9) >> 2;
    const int cmask = (1 << sh) - 1;

    __shared__ int      As[128 * 9];     // [m][k4l], stride 9 words
    __shared__ unsigned Bsm[128 * 9];    // [pix][k4l], stride 9 words

    const int t = threadIdx.x;
    const int bx = blockIdx.x, by = blockIdx.y;
    const int lane = t & 31;
    const int wid  = t >> 5;
    const int gid  = lane >> 2;          // 0..7
    const int tig  = lane & 3;           // 0..3
    const int warp_m = wid >> 2;         // 0..1
    const int warp_n = wid & 3;          // 0..3

    // Hoisted pixel decode for the 4 B-load slots of this thread
    int pn[4], py[4], px[4];
    #pragma unroll
    for (int i = 0; i < 4; i++) {
        int idx = t + i * 256;
        int pl  = idx >> 3;
        int jcol = bx * 128 + pl;
        int n_ = jcol / HW;
        int rem = jcol - n_ * HW;
        pn[i] = n_;
        py[i] = rem / W;
        px[i] = rem - py[i] * W;
    }

    int c[4][4][4];
    #pragma unroll
    for (int am = 0; am < 4; am++)
        #pragma unroll
        for (int an = 0; an < 4; an++)
            #pragma unroll
            for (int q = 0; q < 4; q++) c[am][an][q] = 0;

    const int KT = K4 >> 3;
    for (int kt = 0; kt < KT; ++kt) {
        const int kbase4 = kt * 8;
        // A tile: As[m][k4l] <- wq8[(kbase4+k4l)*COUT + by*128+m]
        #pragma unroll
        for (int i = 0; i < 4; i++) {
            int idx = t + i * 256;
            int m   = idx & 127;
            int k4l = idx >> 7;
            int row = by * 128 + m;
            int v = 0;
            if (row < COUT) v = wq8[(kbase4 + k4l) * COUT + row];
            As[m * 9 + k4l] = v;
        }
        // B tile: Bsm[pix][k4l] <- act word (im2col)
        #pragma unroll
        for (int i = 0; i < 4; i++) {
            int idx = t + i * 256;
            int k4l = idx & 7;
            int pl  = idx >> 3;
            int kg = kbase4 + k4l;
            int rs = kg >> sh;
            int ci = (kg & cmask) << 2;
            int r = rs / 3, s2 = rs - r * 3;
            int yy = py[i] + r - 1;
            int xx = px[i] + s2 - 1;
            unsigned v = 0;
            if (yy >= 0 && yy < H && xx >= 0 && xx < W)
                v = *(const unsigned*)(in + ((size_t)pn[i] * HW + (size_t)yy * W + xx) * CIN + ci);
            Bsm[pl * 9 + k4l] = v;
        }
        __syncthreads();

        int      a[4][4];
        unsigned b[4][2];
        #pragma unroll
        for (int am = 0; am < 4; am++) {
            int r0 = warp_m * 64 + am * 16 + gid;
            a[am][0] = As[r0 * 9 + tig];
            a[am][1] = As[(r0 + 8) * 9 + tig];
            a[am][2] = As[r0 * 9 + tig + 4];
            a[am][3] = As[(r0 + 8) * 9 + tig + 4];
        }
        #pragma unroll
        for (int an = 0; an < 4; an++) {
            int cl = warp_n * 32 + an * 8 + gid;
            b[an][0] = Bsm[cl * 9 + tig];
            b[an][1] = Bsm[cl * 9 + tig + 4];
        }
        #pragma unroll
        for (int am = 0; am < 4; am++)
            #pragma unroll
            for (int an = 0; an < 4; an++)
                imma16832(c[am][an], a[am], b[an]);
        __syncthreads();
    }

    // Epilogue: exact quant via fp64 factor
    const float alpha_a = __ldg(&alphas[layer]);
    const float s_w     = scale_p[2 * layer + 1];
    const float alpha_p = __ldg(&alphas[layer - 1]);
    const double F = (15.0 / (double)alpha_a) / ((double)s_w * (15.0 / (double)alpha_p));

    #pragma unroll
    for (int am = 0; am < 4; am++) {
        int row0 = by * 128 + warp_m * 64 + am * 16 + gid;
        #pragma unroll
        for (int an = 0; an < 4; an++) {
            int colb = bx * 128 + warp_n * 32 + an * 8 + 2 * tig;
            #pragma unroll
            for (int q = 0; q < 4; q++) {
                int row = row0 + (q >> 1) * 8;          // c2,c3 -> +8
                int col = colb + (q & 1);
                if (row >= COUT) continue;
                int n2 = col / HW;
                int rm = col - n2 * HW;
                int yy = rm / W, xx = rm - yy * W;
                double td = (double)c[am][an][q] * F;
                float tq = (float)rint(td);
                tq = fminf(fmaxf(tq, 0.f), 15.f);
                out[(((size_t)n2 * H + yy) * W + xx) * COUT + row] = (uint8_t)tq;
            }
        }
    }
}

// ----------------------------------------------------------------------------
// 2x2 maxpool stride 2 on u8 NHWC
// ----------------------------------------------------------------------------
__global__ void pool8_kernel(const uint8_t* __restrict__ in, uint8_t* __restrict__ out,
                             int C, int Hin) {
    int Hout = Hin >> 1;
    int total = BATCH * Hout * Hout * C;
    int idx = blockIdx.x * blockDim.x + threadIdx.x;
    if (idx >= total) return;
    int c = idx % C;
    int tmp = idx / C;
    int x = tmp % Hout;
    tmp /= Hout;
    int y = tmp % Hout;
    int n = tmp / Hout;
    const uint8_t* p = in + (((size_t)n * Hin + 2 * y) * Hin + 2 * x) * C + c;
    size_t rows = (size_t)Hin * C;
    uint8_t v0 = p[0], v1 = p[C], v2 = p[rows], v3 = p[rows + C];
    uint8_t v = v0 > v1 ? v0 : v1;
    uint8_t w = v2 > v3 ? v2 : v3;
    out[idx] = v > w ? v : w;
}

__global__ void pool_final_kernel(const uint8_t* __restrict__ in, float* __restrict__ out,
                                  const float* __restrict__ alphas) {
    int total = BATCH * 512;
    int idx = blockIdx.x * blockDim.x + threadIdx.x;
    if (idx >= total) return;
    int c = idx & 511;
    int n = idx >> 9;
    const uint8_t* p = in + (size_t)n * 4 * 512 + c;
    uint8_t v0 = p[0], v1 = p[512], v2 = p[1024], v3 = p[1536];
    uint8_t v = v0 > v1 ? v0 : v1;
    uint8_t w = v2 > v3 ? v2 : v3;
    uint8_t m = v > w ? v : w;
    float sc = __fdiv_rn(15.0f, __ldg(&alphas[12]));
    out[idx] = __fdiv_rn((float)m, sc);
}

// ----------------------------------------------------------------------------
// FC: out = act @ w^T + b, optional relu
// ----------------------------------------------------------------------------
__global__ void fc_kernel(const float* __restrict__ act, const float* __restrict__ w,
                          const float* __restrict__ bias, float* __restrict__ out,
                          int M, int N, int K, int dorelu) {
    __shared__ float As[16][16];
    __shared__ float Ws[16][17];
    int row = blockIdx.y * 16 + threadIdx.y;
    int col = blockIdx.x * 16 + threadIdx.x;
    float acc = 0.f;
    for (int kt = 0; kt < K; kt += 16) {
        As[threadIdx.y][threadIdx.x] = (row < M) ? act[row * K + kt + threadIdx.x] : 0.f;
        int wrow = blockIdx.x * 16 + threadIdx.y;
        Ws[threadIdx.y][threadIdx.x] = (wrow < N) ? w[wrow * K + kt + threadIdx.x] : 0.f;
        __syncthreads();
        #pragma unroll
        for (int k = 0; k < 16; k++)
            acc = fmaf(As[threadIdx.y][k], Ws[threadIdx.x][k], acc);
        __syncthreads();
    }
    if (row < M && col < N) {
        acc += bias[col];
        if (dorelu) acc = fmaxf(acc, 0.f);
        out[row * N + col] = acc;
    }
}

// ----------------------------------------------------------------------------
// Host orchestration
// ----------------------------------------------------------------------------
struct LayerCfg { int cin, cout, h; bool pool_after; };
static const LayerCfg g_layers[NLAYERS] = {
    {  3,  64, 32, false},
    { 64,  64, 32, true },
    { 64, 128, 16, false},
    {128, 128, 16, true },
    {128, 256,  8, false},
    {256, 256,  8, false},
    {256, 256,  8, true },
    {256, 512,  4, false},
    {512, 512,  4, false},
    {512, 512,  4, true },
    {512, 512,  2, false},
    {512, 512,  2, false},
    {512, 512,  2, true },
};

static int ilog2(int v) { int r = 0; while ((1 << r) < v) r++; return r; }

extern "C" void kernel_launch(void* const* d_in, const int* in_sizes, int n_in,
                              void* d_out, int out_size) {
    (void)in_sizes; (void)n_in; (void)out_size;

    const float* x      = (const float*)d_in[0];
    const float* convw[NLAYERS];
    for (int i = 0; i < NLAYERS; i++) convw[i] = (const float*)d_in[1 + i];
    const float* alphas = (const float*)d_in[14];
    const float* fc1_w  = (const float*)d_in[15];
    const float* fc1_b  = (const float*)d_in[16];
    const float* fc2_w  = (const float*)d_in[17];
    const float* fc2_b  = (const float*)d_in[18];
    const float* fc3_w  = (const float*)d_in[19];
    const float* fc3_b  = (const float*)d_in[20];

    uint8_t *a8A, *a8B;
    float *fc0, *fcA, *fcB, *wq0, *scale;
    int *wq8;
    double *partial;
    cudaGetSymbolAddress((void**)&a8A,     g_act8A);
    cudaGetSymbolAddress((void**)&a8B,     g_act8B);
    cudaGetSymbolAddress((void**)&fc0,     g_fc0);
    cudaGetSymbolAddress((void**)&fcA,     g_fcA);
    cudaGetSymbolAddress((void**)&fcB,     g_fcB);
    cudaGetSymbolAddress((void**)&wq0,     g_wq0);
    cudaGetSymbolAddress((void**)&wq8,     g_wq8);
    cudaGetSymbolAddress((void**)&partial, g_partial);
    cudaGetSymbolAddress((void**)&scale,   g_scale);

    long w8off[NLAYERS];
    long acc_off = 0;
    for (int i = 1; i < NLAYERS; i++) {
        w8off[i] = acc_off;
        acc_off += (long)((g_layers[i].cin * 9) >> 2) * g_layers[i].cout;
    }

    for (int i = 0; i < NLAYERS; i++) {
        int n = g_layers[i].cout * g_layers[i].cin * 9;
        absum_kernel<<<256, 256>>>(convw[i], n, partial + i * 256);
        finalize_kernel<<<1, 256>>>(partial + i * 256, n, scale + i * 2);
    }
    quantw0_kernel<<<(27 * 64 + 255) / 256, 256>>>(convw[0], 27 * 64, 27, 64, scale, wq0);
    for (int i = 1; i < NLAYERS; i++) {
        int K4 = (g_layers[i].cin * 9) >> 2;
        int total = K4 * g_layers[i].cout;
        quantw_pack_kernel<<<(total + 255) / 256, 256>>>(convw[i], g_layers[i].cin,
                                                         g_layers[i].cout, scale + i * 2,
                                                         wq8 + w8off[i]);
    }

    {
        int N = BATCH * 32 * 32;
        conv0_kernel<<<dim3(N / 128, 1), 256>>>(x, wq0, a8A, alphas, scale);
    }

    uint8_t* buf[2] = {a8A, a8B};
    int cur = 0;

    for (int i = 1; i < NLAYERS; i++) {
        const LayerCfg& L = g_layers[i];
        int N = BATCH * L.h * L.h;
        int dst = 1 - cur;
        int sh = ilog2(L.cin >> 2);
        dim3 grid(N / 128, (L.cout + 127) / 128);
        conv_imma_kernel<<<grid, 256>>>(buf[cur], wq8 + w8off[i], buf[dst],
                                        L.cin, L.cout, L.h, sh, alphas, scale, i);
        cur = dst;
        if (L.pool_after) {
            if (i == NLAYERS - 1) {
                pool_final_kernel<<<(BATCH * 512 + 255) / 256, 256>>>(buf[cur], fc0, alphas);
            } else {
                int dst2 = 1 - cur;
                int Hout = L.h >> 1;
                int total = BATCH * Hout * Hout * L.cout;
                pool8_kernel<<<(total + 255) / 256, 256>>>(buf[cur], buf[dst2], L.cout, L.h);
                cur = dst2;
            }
        }
    }

    {
        dim3 grid1((512 + 15) / 16, (BATCH + 15) / 16);
        fc_kernel<<<grid1, dim3(16, 16)>>>(fc0, fc1_w, fc1_b, fcA, BATCH, 512, 512, 1);
        fc_kernel<<<grid1, dim3(16, 16)>>>(fcA, fc2_w, fc2_b, fcB, BATCH, 512, 512, 1);
        dim3 grid3(1, (BATCH + 15) / 16);
        fc_kernel<<<grid3, dim3(16, 16)>>>(fcB, fc3_w, fc3_b, (float*)d_out, BATCH, 10, 512, 0);
    }
}

// round 9
// speedup vs baseline: 5.6707x; 1.0122x over previous
#include <cuda_runtime.h>
#include <cstdint>

// ============================================================================
// Quantized VGG forward (batch 512) — integer levels end-to-end.
// Convs 1-12: IMMA mma.sync m16n8k32 (s8 x u8 -> s32, exact), cp.async
// double-buffered, templated N-tile for small-layer occupancy.
// Acts: u8 NHWC levels (0..15). Weights: s8 levels packed 4/word [K4][Cout].
// Epilogue quant via fp64 factor (bit-exact decisions -> rel_err 0.0).
// ============================================================================

#define BATCH 512
#define NLAYERS 13

#define ACT8_ELEMS (512*64*32*32)
#define WQ8_WORDS  4000000

__device__ uint8_t g_act8A[ACT8_ELEMS];
__device__ uint8_t g_act8B[ACT8_ELEMS];
__device__ float   g_fc0[BATCH * 512];
__device__ float   g_fcA[BATCH * 512];
__device__ float   g_fcB[BATCH * 512];
__device__ float   g_wq0[27 * 64];
__device__ int     g_wq8[WQ8_WORDS];
__device__ double  g_partial[NLAYERS * 256];
__device__ float   g_scale[NLAYERS * 2];

// ----------------------------------------------------------------------------
// cp.async helpers
// ----------------------------------------------------------------------------
__device__ __forceinline__ void cp4(uint32_t saddr, const void* g, unsigned sz) {
    asm volatile("cp.async.ca.shared.global [%0], [%1], 4, %2;"
                 :: "r"(saddr), "l"(g), "r"(sz) : "memory");
}
__device__ __forceinline__ void cp_commit() {
    asm volatile("cp.async.commit_group;" ::: "memory");
}
__device__ __forceinline__ void cp_wait0() {
    asm volatile("cp.async.wait_group 0;" ::: "memory");
}

__device__ __forceinline__ void imma16832(int* c, const int* a, const unsigned* b) {
    asm volatile(
        "mma.sync.aligned.m16n8k32.row.col.s32.s8.u8.s32 "
        "{%0,%1,%2,%3}, {%4,%5,%6,%7}, {%8,%9}, {%0,%1,%2,%3};"
        : "+r"(c[0]), "+r"(c[1]), "+r"(c[2]), "+r"(c[3])
        : "r"(a[0]), "r"(a[1]), "r"(a[2]), "r"(a[3]),
          "r"(b[0]), "r"(b[1]));
}

// ----------------------------------------------------------------------------
// Weight scale pipeline (unchanged — rel_err 0.0 verified)
// ----------------------------------------------------------------------------
__global__ void absum_kernel(const float* __restrict__ w, int n, double* __restrict__ partial) {
    __shared__ double s[256];
    double acc = 0.0;
    for (int i = blockIdx.x * 256 + threadIdx.x; i < n; i += 256 * 256)
        acc += (double)fabsf(w[i]);
    s[threadIdx.x] = acc;
    __syncthreads();
    for (int o = 128; o > 0; o >>= 1) {
        if (threadIdx.x < o) s[threadIdx.x] += s[threadIdx.x + o];
        __syncthreads();
    }
    if (threadIdx.x == 0) partial[blockIdx.x] = s[0];
}

__global__ void finalize_kernel(const double* __restrict__ partial, int n, float* __restrict__ scale_out) {
    __shared__ double s[256];
    s[threadIdx.x] = partial[threadIdx.x];
    __syncthreads();
    for (int o = 128; o > 0; o >>= 1) {
        if (threadIdx.x < o) s[threadIdx.x] += s[threadIdx.x + o];
        __syncthreads();
    }
    if (threadIdx.x == 0) {
        float sum_f = (float)s[0];
        float mean  = __fdiv_rn(sum_f, (float)n);
        float alpha = 2.0f * mean;
        float sw    = __fdiv_rn(7.0f, alpha);
        scale_out[0] = alpha;
        scale_out[1] = sw;
    }
}

__global__ void quantw0_kernel(const float* __restrict__ w, int n, int K, int Cout,
                               const float* __restrict__ scale_p, float* __restrict__ wq_t) {
    int idx = blockIdx.x * blockDim.x + threadIdx.x;
    if (idx >= n) return;
    float alpha = scale_p[0];
    float s     = scale_p[1];
    float wc = fminf(fmaxf(w[idx], -alpha), alpha);
    float m  = rintf(wc * s);
    int mo = idx / K;
    int k  = idx - mo * K;
    wq_t[k * Cout + mo] = m;
}

__global__ void quantw_pack_kernel(const float* __restrict__ w, int CIN, int Cout,
                                   const float* __restrict__ scale_p, int* __restrict__ wq8) {
    int K4 = (CIN * 9) >> 2;
    int total = K4 * Cout;
    int idx = blockIdx.x * blockDim.x + threadIdx.x;
    if (idx >= total) return;
    int k4 = idx / Cout;
    int m  = idx - k4 * Cout;
    int cin4 = CIN >> 2;
    int rs = k4 / cin4;
    int ci0 = (k4 - rs * cin4) << 2;
    int r = rs / 3;
    int s2 = rs - r * 3;
    float alpha = scale_p[0];
    float s = scale_p[1];
    unsigned pack = 0;
    #pragma unroll
    for (int t = 0; t < 4; t++) {
        int ci = ci0 + t;
        float v = w[((m * CIN + ci) * 3 + r) * 3 + s2];
        float wc = fminf(fmaxf(v, -alpha), alpha);
        int mi = (int)rintf(wc * s);
        pack |= ((unsigned)(mi & 0xFF)) << (8 * t);
    }
    wq8[k4 * Cout + m] = (int)pack;
}

// ----------------------------------------------------------------------------
// Layer 0 conv: fp32 GEMM (K=27), x NCHW fp32 -> u8 NHWC levels
// ----------------------------------------------------------------------------
__global__ __launch_bounds__(256) void conv0_kernel(
    const float* __restrict__ x, const float* __restrict__ wq_t,
    uint8_t* __restrict__ out,
    const float* __restrict__ alphas, const float* __restrict__ scale_p)
{
    const int CIN = 3, COUT = 64, H = 32, W = 32, HW = 1024;
    const int K = 27;

    __shared__ float As[8][128];
    __shared__ float Bs[8][128];

    const int t = threadIdx.x;
    const int bx = blockIdx.x;

    const int lcol = t & 127;
    const int kl   = t >> 7;
    const int jcol = bx * 128 + lcol;
    int n_ = jcol / HW;
    int rem = jcol - n_ * HW;
    int y_ = rem >> 5;
    int x_ = rem & 31;
    const float* inbase = x + (size_t)n_ * CIN * HW;

    const int arow = lcol;
    const bool avalid = (arow < COUT);

    float acc[8][8];
    #pragma unroll
    for (int i = 0; i < 8; i++)
        #pragma unroll
        for (int j = 0; j < 8; j++) acc[i][j] = 0.f;

    const int tm0 = (t & 15) * 8;
    const int tn0 = (t >> 4) * 8;

    for (int kt = 0; kt < 4; ++kt) {
        const int kbase = kt * 8;
        #pragma unroll
        for (int i = 0; i < 4; i++) {
            int kk = kl + 2 * i;
            int kg = kbase + kk;
            float v = 0.f;
            if (avalid && kg < K) v = wq_t[kg * COUT + arow];
            As[kk][lcol] = v;
        }
        #pragma unroll
        for (int i = 0; i < 4; i++) {
            int kk = kl + 2 * i;
            int kg = kbase + kk;
            float v = 0.f;
            if (kg < K) {
                int ci = kg / 9;
                int rs = kg - ci * 9;
                int r = rs / 3;
                int s2 = rs - r * 3;
                int yy = y_ + r - 1;
                int xx = x_ + s2 - 1;
                if (yy >= 0 && yy < H && xx >= 0 && xx < W)
                    v = inbase[ci * HW + yy * W + xx];
            }
            Bs[kk][lcol] = v;
        }
        __syncthreads();
        #pragma unroll
        for (int kk = 0; kk < 8; kk++) {
            float a[8], b[8];
            #pragma unroll
            for (int i = 0; i < 8; i++) a[i] = As[kk][tm0 + i];
            #pragma unroll
            for (int j = 0; j < 8; j++) b[j] = Bs[kk][tn0 + j];
            #pragma unroll
            for (int i = 0; i < 8; i++)
                #pragma unroll
                for (int j = 0; j < 8; j++)
                    acc[i][j] = fmaf(a[i], b[j], acc[i][j]);
        }
        __syncthreads();
    }

    const float alpha_a = __ldg(&alphas[0]);
    const float s_w     = scale_p[1];
    const double F = (15.0 / (double)alpha_a) / (double)s_w;

    #pragma unroll
    for (int i = 0; i < 8; i++) {
        int m = tm0 + i;
        if (m >= COUT) continue;
        #pragma unroll
        for (int j = 0; j < 8; j++) {
            int jj = bx * 128 + tn0 + j;
            int n2 = jj / HW;
            int rm = jj - n2 * HW;
            int yy = rm >> 5, xx = rm & 31;
            double td = (double)acc[i][j] * F;
            float tq = (float)rint(td);
            tq = fminf(fmaxf(tq, 0.f), 15.f);
            out[(((size_t)n2 * H + yy) * W + xx) * COUT + m] = (uint8_t)tq;
        }
    }
}

// ----------------------------------------------------------------------------
// IMMA conv, double-buffered cp.async. Block tile 128 x NBLK, 256 threads,
// warp grid WM x WN (WM*WN=8). Warp tile (128/WM) x (NBLK/WN).
// ----------------------------------------------------------------------------
template<int NBLK, int WM, int WN>
__global__ __launch_bounds__(256) void conv_imma_db_kernel(
    const uint8_t* __restrict__ in, const int* __restrict__ wq8,
    uint8_t* __restrict__ out, int CIN, int COUT, int H, int sh,
    const float* __restrict__ alphas, const float* __restrict__ scale_p, int layer)
{
    constexpr int AM = (128 / WM) / 16;   // m16 atoms per warp
    constexpr int AN = (NBLK / WN) / 8;   // n8 atoms per warp
    constexpr int BLOADS = NBLK / 32;     // B words per thread per stage

    const int W = H, HW = H * H;
    const int K4 = (CIN * 9) >> 2;
    const int cmask = (1 << sh) - 1;

    __shared__ int      As[2][128 * 9];
    __shared__ unsigned Bsm[2][NBLK * 9];

    const int t = threadIdx.x;
    const int bx = blockIdx.x, by = blockIdx.y;
    const int lane = t & 31;
    const int wid  = t >> 5;
    const int gid  = lane >> 2;
    const int tig  = lane & 3;
    const int warp_m = wid / WN;
    const int warp_n = wid - warp_m * WN;

    // Hoisted pixel decode for B-load slots
    int pn[BLOADS], py[BLOADS], px[BLOADS];
    #pragma unroll
    for (int i = 0; i < BLOADS; i++) {
        int idx = t + i * 256;
        int pl  = idx >> 3;
        int jcol = bx * NBLK + pl;
        int n_ = jcol / HW;
        int rem = jcol - n_ * HW;
        pn[i] = n_;
        py[i] = rem / W;
        px[i] = rem - py[i] * W;
    }
    // A-load row validity (hoisted)
    int arow_[4]; unsigned asz[4];
    #pragma unroll
    for (int i = 0; i < 4; i++) {
        int idx = t + i * 256;
        int m   = idx & 127;
        arow_[i] = by * 128 + m;
        asz[i]   = (arow_[i] < COUT) ? 4u : 0u;
    }

    uint32_t sA[2], sB[2];
    sA[0] = (uint32_t)__cvta_generic_to_shared(&As[0][0]);
    sA[1] = (uint32_t)__cvta_generic_to_shared(&As[1][0]);
    sB[0] = (uint32_t)__cvta_generic_to_shared(&Bsm[0][0]);
    sB[1] = (uint32_t)__cvta_generic_to_shared(&Bsm[1][0]);

    int c[AM][AN][4];
    #pragma unroll
    for (int am = 0; am < AM; am++)
        #pragma unroll
        for (int an = 0; an < AN; an++)
            #pragma unroll
            for (int q = 0; q < 4; q++) c[am][an][q] = 0;

    const int KT = K4 >> 3;

    // Stage loader
    auto load_stage = [&](int kt, int buf) {
        const int kbase4 = kt * 8;
        // A tile
        #pragma unroll
        for (int i = 0; i < 4; i++) {
            int idx = t + i * 256;
            int m   = idx & 127;
            int k4l = idx >> 7;
            const void* g = (asz[i] ? (const void*)&wq8[(kbase4 + k4l) * COUT + arow_[i]]
                                    : (const void*)wq8);
            cp4(sA[buf] + (m * 9 + k4l) * 4, g, asz[i]);
        }
        // B tile (im2col)
        #pragma unroll
        for (int i = 0; i < BLOADS; i++) {
            int idx = t + i * 256;
            int k4l = idx & 7;
            int pl  = idx >> 3;
            int kg = kbase4 + k4l;
            int rs = kg >> sh;
            int ci = (kg & cmask) << 2;
            int r = rs / 3, s2 = rs - r * 3;
            int yy = py[i] + r - 1;
            int xx = px[i] + s2 - 1;
            bool ok = (yy >= 0 && yy < H && xx >= 0 && xx < W);
            const void* g = ok ? (const void*)(in + ((size_t)pn[i] * HW + (size_t)yy * W + xx) * CIN + ci)
                               : (const void*)in;
            cp4(sB[buf] + (pl * 9 + k4l) * 4, g, ok ? 4u : 0u);
        }
        cp_commit();
    };

    load_stage(0, 0);

    for (int kt = 0; kt < KT; ++kt) {
        const int buf = kt & 1;
        cp_wait0();
        __syncthreads();
        if (kt + 1 < KT) load_stage(kt + 1, buf ^ 1);

        const int*      Ab = &As[buf][0];
        const unsigned* Bb = &Bsm[buf][0];

        int      a[AM][4];
        unsigned b[AN][2];
        #pragma unroll
        for (int am = 0; am < AM; am++) {
            int r0 = warp_m * (128 / WM) + am * 16 + gid;
            a[am][0] = Ab[r0 * 9 + tig];
            a[am][1] = Ab[(r0 + 8) * 9 + tig];
            a[am][2] = Ab[r0 * 9 + tig + 4];
            a[am][3] = Ab[(r0 + 8) * 9 + tig + 4];
        }
        #pragma unroll
        for (int an = 0; an < AN; an++) {
            int cl = warp_n * (NBLK / WN) + an * 8 + gid;
            b[an][0] = Bb[cl * 9 + tig];
            b[an][1] = Bb[cl * 9 + tig + 4];
        }
        #pragma unroll
        for (int am = 0; am < AM; am++)
            #pragma unroll
            for (int an = 0; an < AN; an++)
                imma16832(c[am][an], a[am], b[an]);
        __syncthreads();
    }

    // Epilogue: exact quant via fp64 factor
    const float alpha_a = __ldg(&alphas[layer]);
    const float s_w     = scale_p[2 * layer + 1];
    const float alpha_p = __ldg(&alphas[layer - 1]);
    const double F = (15.0 / (double)alpha_a) / ((double)s_w * (15.0 / (double)alpha_p));

    #pragma unroll
    for (int am = 0; am < AM; am++) {
        int row0 = by * 128 + warp_m * (128 / WM) + am * 16 + gid;
        #pragma unroll
        for (int an = 0; an < AN; an++) {
            int colb = bx * NBLK + warp_n * (NBLK / WN) + an * 8 + 2 * tig;
            #pragma unroll
            for (int q = 0; q < 4; q++) {
                int row = row0 + (q >> 1) * 8;
                int col = colb + (q & 1);
                if (row >= COUT) continue;
                int n2 = col / HW;
                int rm = col - n2 * HW;
                int yy = rm / W, xx = rm - yy * W;
                double td = (double)c[am][an][q] * F;
                float tq = (float)rint(td);
                tq = fminf(fmaxf(tq, 0.f), 15.f);
                out[(((size_t)n2 * H + yy) * W + xx) * COUT + row] = (uint8_t)tq;
            }
        }
    }
}

// ----------------------------------------------------------------------------
// Pools
// ----------------------------------------------------------------------------
__global__ void pool8_kernel(const uint8_t* __restrict__ in, uint8_t* __restrict__ out,
                             int C, int Hin) {
    int Hout = Hin >> 1;
    int total = BATCH * Hout * Hout * C;
    int idx = blockIdx.x * blockDim.x + threadIdx.x;
    if (idx >= total) return;
    int c = idx % C;
    int tmp = idx / C;
    int x = tmp % Hout;
    tmp /= Hout;
    int y = tmp % Hout;
    int n = tmp / Hout;
    const uint8_t* p = in + (((size_t)n * Hin + 2 * y) * Hin + 2 * x) * C + c;
    size_t rows = (size_t)Hin * C;
    uint8_t v0 = p[0], v1 = p[C], v2 = p[rows], v3 = p[rows + C];
    uint8_t v = v0 > v1 ? v0 : v1;
    uint8_t w = v2 > v3 ? v2 : v3;
    out[idx] = v > w ? v : w;
}

__global__ void pool_final_kernel(const uint8_t* __restrict__ in, float* __restrict__ out,
                                  const float* __restrict__ alphas) {
    int total = BATCH * 512;
    int idx = blockIdx.x * blockDim.x + threadIdx.x;
    if (idx >= total) return;
    int c = idx & 511;
    int n = idx >> 9;
    const uint8_t* p = in + (size_t)n * 4 * 512 + c;
    uint8_t v0 = p[0], v1 = p[512], v2 = p[1024], v3 = p[1536];
    uint8_t v = v0 > v1 ? v0 : v1;
    uint8_t w = v2 > v3 ? v2 : v3;
    uint8_t m = v > w ? v : w;
    float sc = __fdiv_rn(15.0f, __ldg(&alphas[12]));
    out[idx] = __fdiv_rn((float)m, sc);
}

// ----------------------------------------------------------------------------
// FC
// ----------------------------------------------------------------------------
__global__ void fc_kernel(const float* __restrict__ act, const float* __restrict__ w,
                          const float* __restrict__ bias, float* __restrict__ out,
                          int M, int N, int K, int dorelu) {
    __shared__ float As[16][16];
    __shared__ float Ws[16][17];
    int row = blockIdx.y * 16 + threadIdx.y;
    int col = blockIdx.x * 16 + threadIdx.x;
    float acc = 0.f;
    for (int kt = 0; kt < K; kt += 16) {
        As[threadIdx.y][threadIdx.x] = (row < M) ? act[row * K + kt + threadIdx.x] : 0.f;
        int wrow = blockIdx.x * 16 + threadIdx.y;
        Ws[threadIdx.y][threadIdx.x] = (wrow < N) ? w[wrow * K + kt + threadIdx.x] : 0.f;
        __syncthreads();
        #pragma unroll
        for (int k = 0; k < 16; k++)
            acc = fmaf(As[threadIdx.y][k], Ws[threadIdx.x][k], acc);
        __syncthreads();
    }
    if (row < M && col < N) {
        acc += bias[col];
        if (dorelu) acc = fmaxf(acc, 0.f);
        out[row * N + col] = acc;
    }
}

// ----------------------------------------------------------------------------
// Host orchestration
// ----------------------------------------------------------------------------
struct LayerCfg { int cin, cout, h; bool pool_after; };
static const LayerCfg g_layers[NLAYERS] = {
    {  3,  64, 32, false},
    { 64,  64, 32, true },
    { 64, 128, 16, false},
    {128, 128, 16, true },
    {128, 256,  8, false},
    {256, 256,  8, false},
    {256, 256,  8, true },
    {256, 512,  4, false},
    {512, 512,  4, false},
    {512, 512,  4, true },
    {512, 512,  2, false},
    {512, 512,  2, false},
    {512, 512,  2, true },
};

static int ilog2(int v) { int r = 0; while ((1 << r) < v) r++; return r; }

extern "C" void kernel_launch(void* const* d_in, const int* in_sizes, int n_in,
                              void* d_out, int out_size) {
    (void)in_sizes; (void)n_in; (void)out_size;

    const float* x      = (const float*)d_in[0];
    const float* convw[NLAYERS];
    for (int i = 0; i < NLAYERS; i++) convw[i] = (const float*)d_in[1 + i];
    const float* alphas = (const float*)d_in[14];
    const float* fc1_w  = (const float*)d_in[15];
    const float* fc1_b  = (const float*)d_in[16];
    const float* fc2_w  = (const float*)d_in[17];
    const float* fc2_b  = (const float*)d_in[18];
    const float* fc3_w  = (const float*)d_in[19];
    const float* fc3_b  = (const float*)d_in[20];

    uint8_t *a8A, *a8B;
    float *fc0, *fcA, *fcB, *wq0, *scale;
    int *wq8;
    double *partial;
    cudaGetSymbolAddress((void**)&a8A,     g_act8A);
    cudaGetSymbolAddress((void**)&a8B,     g_act8B);
    cudaGetSymbolAddress((void**)&fc0,     g_fc0);
    cudaGetSymbolAddress((void**)&fcA,     g_fcA);
    cudaGetSymbolAddress((void**)&fcB,     g_fcB);
    cudaGetSymbolAddress((void**)&wq0,     g_wq0);
    cudaGetSymbolAddress((void**)&wq8,     g_wq8);
    cudaGetSymbolAddress((void**)&partial, g_partial);
    cudaGetSymbolAddress((void**)&scale,   g_scale);

    long w8off[NLAYERS];
    long acc_off = 0;
    for (int i = 1; i < NLAYERS; i++) {
        w8off[i] = acc_off;
        acc_off += (long)((g_layers[i].cin * 9) >> 2) * g_layers[i].cout;
    }

    for (int i = 0; i < NLAYERS; i++) {
        int n = g_layers[i].cout * g_layers[i].cin * 9;
        absum_kernel<<<256, 256>>>(convw[i], n, partial + i * 256);
        finalize_kernel<<<1, 256>>>(partial + i * 256, n, scale + i * 2);
    }
    quantw0_kernel<<<(27 * 64 + 255) / 256, 256>>>(convw[0], 27 * 64, 27, 64, scale, wq0);
    for (int i = 1; i < NLAYERS; i++) {
        int K4 = (g_layers[i].cin * 9) >> 2;
        int total = K4 * g_layers[i].cout;
        quantw_pack_kernel<<<(total + 255) / 256, 256>>>(convw[i], g_layers[i].cin,
                                                         g_layers[i].cout, scale + i * 2,
                                                         wq8 + w8off[i]);
    }

    {
        int N = BATCH * 32 * 32;
        conv0_kernel<<<dim3(N / 128, 1), 256>>>(x, wq0, a8A, alphas, scale);
    }

    uint8_t* buf[2] = {a8A, a8B};
    int cur = 0;

    for (int i = 1; i < NLAYERS; i++) {
        const LayerCfg& L = g_layers[i];
        int N = BATCH * L.h * L.h;
        int dst = 1 - cur;
        int sh = ilog2(L.cin >> 2);
        int gy = (L.cout + 127) / 128;
        // Choose N-tile so the grid fills the chip
        if ((N / 128) * gy >= 120) {
            dim3 grid(N / 128, gy);
            conv_imma_db_kernel<128, 2, 4><<<grid, 256>>>(buf[cur], wq8 + w8off[i], buf[dst],
                                                          L.cin, L.cout, L.h, sh, alphas, scale, i);
        } else {
            dim3 grid(N / 64, gy);
            conv_imma_db_kernel<64, 4, 2><<<grid, 256>>>(buf[cur], wq8 + w8off[i], buf[dst],
                                                         L.cin, L.cout, L.h, sh, alphas, scale, i);
        }
        cur = dst;
        if (L.pool_after) {
            if (i == NLAYERS - 1) {
                pool_final_kernel<<<(BATCH * 512 + 255) / 256, 256>>>(buf[cur], fc0, alphas);
            } else {
                int dst2 = 1 - cur;
                int Hout = L.h >> 1;
                int total = BATCH * Hout * Hout * L.cout;
                pool8_kernel<<<(total + 255) / 256, 256>>>(buf[cur], buf[dst2], L.cout, L.h);
                cur = dst2;
            }
        }
    }

    {
        dim3 grid1((512 + 15) / 16, (BATCH + 15) / 16);
        fc_kernel<<<grid1, dim3(16, 16)>>>(fc0, fc1_w, fc1_b, fcA, BATCH, 512, 512, 1);
        fc_kernel<<<grid1, dim3(16, 16)>>>(fcA, fc2_w, fc2_b, fcB, BATCH, 512, 512, 1);
        dim3 grid3(1, (BATCH + 15) / 16);
        fc_kernel<<<grid3, dim3(16, 16)>>>(fcB, fc3_w, fc3_b, (float*)d_out, BATCH, 10, 512, 0);
    }
}

// round 10
// speedup vs baseline: 7.9921x; 1.4094x over previous
#include <cuda_runtime.h>
#include <cstdint>

// ============================================================================
// Quantized VGG forward (batch 512) — integer levels end-to-end.
// Convs 1-12: IMMA m16n8k32 (s8 x u8 -> s32, exact). Weights pre-packed in
// mma FRAGMENT ORDER (one LDS.128 per atom); B im2col staged as 16B cp.async
// (contiguous channel segments). Epilogue quant via fp64 factor (exact).
// ============================================================================

#define BATCH 512
#define NLAYERS 13

#define ACT8_ELEMS (512*64*32*32)
#define WQ8_WORDS  4000000

__device__ uint8_t g_act8A[ACT8_ELEMS];
__device__ uint8_t g_act8B[ACT8_ELEMS];
__device__ float   g_fc0[BATCH * 512];
__device__ float   g_fcA[BATCH * 512];
__device__ float   g_fcB[BATCH * 512];
__device__ float   g_wq0[27 * 64];
__device__ int     g_wq8[WQ8_WORDS];      // fragment-ordered packed s8 weights
__device__ double  g_partial[NLAYERS * 256];
__device__ float   g_scale[NLAYERS * 2];

struct AbsArgs  { const float* p[13]; int n[13]; };
struct PackArgs { const float* w[12]; long off[12]; int cin[12]; int cout[12];
                  int coutp[12]; int sh[12]; int nwords[12]; };

// ----------------------------------------------------------------------------
// asm helpers
// ----------------------------------------------------------------------------
__device__ __forceinline__ void cp16(uint32_t saddr, const void* g, unsigned sz) {
    asm volatile("cp.async.cg.shared.global [%0], [%1], 16, %2;"
                 :: "r"(saddr), "l"(g), "r"(sz) : "memory");
}
__device__ __forceinline__ void cp_commit() {
    asm volatile("cp.async.commit_group;" ::: "memory");
}
__device__ __forceinline__ void cp_wait0() {
    asm volatile("cp.async.wait_group 0;" ::: "memory");
}
__device__ __forceinline__ void imma16832(int* c, const int* a, const unsigned* b) {
    asm volatile(
        "mma.sync.aligned.m16n8k32.row.col.s32.s8.u8.s32 "
        "{%0,%1,%2,%3}, {%4,%5,%6,%7}, {%8,%9}, {%0,%1,%2,%3};"
        : "+r"(c[0]), "+r"(c[1]), "+r"(c[2]), "+r"(c[3])
        : "r"(a[0]), "r"(a[1]), "r"(a[2]), "r"(a[3]),
          "r"(b[0]), "r"(b[1]));
}

// ----------------------------------------------------------------------------
// Fused prep: abs-sum (all 13 layers), finalize (all), fragment pack (1-12)
// Identical reduction order to the verified R6-R9 pipeline -> same scale bits.
// ----------------------------------------------------------------------------
__global__ void absum_all_kernel(AbsArgs aa, double* __restrict__ partial) {
    int layer = blockIdx.y;
    const float* w = aa.p[layer];
    int n = aa.n[layer];
    __shared__ double s[256];
    double acc = 0.0;
    for (int i = blockIdx.x * 256 + threadIdx.x; i < n; i += 256 * 256)
        acc += (double)fabsf(w[i]);
    s[threadIdx.x] = acc;
    __syncthreads();
    for (int o = 128; o > 0; o >>= 1) {
        if (threadIdx.x < o) s[threadIdx.x] += s[threadIdx.x + o];
        __syncthreads();
    }
    if (threadIdx.x == 0) partial[layer * 256 + blockIdx.x] = s[0];
}

__global__ void finalize_all_kernel(AbsArgs aa, const double* __restrict__ partial,
                                    float* __restrict__ scale_out) {
    int layer = blockIdx.x;
    __shared__ double s[256];
    s[threadIdx.x] = partial[layer * 256 + threadIdx.x];
    __syncthreads();
    for (int o = 128; o > 0; o >>= 1) {
        if (threadIdx.x < o) s[threadIdx.x] += s[threadIdx.x + o];
        __syncthreads();
    }
    if (threadIdx.x == 0) {
        float sum_f = (float)s[0];
        float mean  = __fdiv_rn(sum_f, (float)aa.n[layer]);
        float alpha = 2.0f * mean;
        float sw    = __fdiv_rn(7.0f, alpha);
        scale_out[layer * 2 + 0] = alpha;
        scale_out[layer * 2 + 1] = sw;
    }
}

__global__ void quantw0_kernel(const float* __restrict__ w, int n, int K, int Cout,
                               const float* __restrict__ scale_p, float* __restrict__ wq_t) {
    int idx = blockIdx.x * blockDim.x + threadIdx.x;
    if (idx >= n) return;
    float alpha = scale_p[0];
    float s     = scale_p[1];
    float wc = fminf(fmaxf(w[idx], -alpha), alpha);
    float m  = rintf(wc * s);
    int mo = idx / K;
    int k  = idx - mo * K;
    wq_t[k * Cout + mo] = m;
}

// Fragment-ordered pack: word index = ((kt*nrb + rblk)*128 + lane*4 + q)
// lane: gid = lane>>2, tig = lane&3 (matches mma lane mapping)
// q: row = rblk*16 + (q&1)*8 + gid ; k4 = kt*8 + (q>>1)*4 + tig
__global__ void pack_frag_kernel(PackArgs pa, const float* __restrict__ scale,
                                 int* __restrict__ wq8) {
    int layer = blockIdx.y;                 // 0..11 -> real layer = layer+1
    int nw = pa.nwords[layer];
    int idx = blockIdx.x * 256 + threadIdx.x;
    if (idx >= nw) return;
    int q    = idx & 3;
    int lane = (idx >> 2) & 31;
    int blk  = idx >> 7;
    int nrb  = pa.coutp[layer] >> 4;
    int kt   = blk / nrb;
    int rblk = blk - kt * nrb;
    int gid = lane >> 2, tig = lane & 3;
    int row = rblk * 16 + ((q & 1) << 3) + gid;
    int k4  = kt * 8 + ((q >> 1) << 2) + tig;
    int val = 0;
    int COUT = pa.cout[layer];
    if (row < COUT) {
        int CIN = pa.cin[layer];
        int sh = pa.sh[layer];
        int cmask = (1 << sh) - 1;
        int rs = k4 >> sh;
        int ci0 = (k4 & cmask) << 2;
        int r = rs / 3, s2 = rs - r * 3;
        float alpha = scale[(layer + 1) * 2 + 0];
        float s     = scale[(layer + 1) * 2 + 1];
        const float* w = pa.w[layer];
        unsigned pack = 0;
        #pragma unroll
        for (int t = 0; t < 4; t++) {
            int ci = ci0 + t;
            float v = w[((row * CIN + ci) * 3 + r) * 3 + s2];
            float wc = fminf(fmaxf(v, -alpha), alpha);
            int mi = (int)rintf(wc * s);
            pack |= ((unsigned)(mi & 0xFF)) << (8 * t);
        }
        val = (int)pack;
    }
    wq8[pa.off[layer] + idx] = val;
}

// ----------------------------------------------------------------------------
// Layer 0 conv: fp32 GEMM (K=27), x NCHW fp32 -> u8 NHWC levels (unchanged)
// ----------------------------------------------------------------------------
__global__ __launch_bounds__(256) void conv0_kernel(
    const float* __restrict__ x, const float* __restrict__ wq_t,
    uint8_t* __restrict__ out,
    const float* __restrict__ alphas, const float* __restrict__ scale_p)
{
    const int CIN = 3, COUT = 64, H = 32, W = 32, HW = 1024;
    const int K = 27;

    __shared__ float As[8][128];
    __shared__ float Bs[8][128];

    const int t = threadIdx.x;
    const int bx = blockIdx.x;

    const int lcol = t & 127;
    const int kl   = t >> 7;
    const int jcol = bx * 128 + lcol;
    int n_ = jcol / HW;
    int rem = jcol - n_ * HW;
    int y_ = rem >> 5;
    int x_ = rem & 31;
    const float* inbase = x + (size_t)n_ * CIN * HW;

    const int arow = lcol;
    const bool avalid = (arow < COUT);

    float acc[8][8];
    #pragma unroll
    for (int i = 0; i < 8; i++)
        #pragma unroll
        for (int j = 0; j < 8; j++) acc[i][j] = 0.f;

    const int tm0 = (t & 15) * 8;
    const int tn0 = (t >> 4) * 8;

    for (int kt = 0; kt < 4; ++kt) {
        const int kbase = kt * 8;
        #pragma unroll
        for (int i = 0; i < 4; i++) {
            int kk = kl + 2 * i;
            int kg = kbase + kk;
            float v = 0.f;
            if (avalid && kg < K) v = wq_t[kg * COUT + arow];
            As[kk][lcol] = v;
        }
        #pragma unroll
        for (int i = 0; i < 4; i++) {
            int kk = kl + 2 * i;
            int kg = kbase + kk;
            float v = 0.f;
            if (kg < K) {
                int ci = kg / 9;
                int rs = kg - ci * 9;
                int r = rs / 3;
                int s2 = rs - r * 3;
                int yy = y_ + r - 1;
                int xx = x_ + s2 - 1;
                if (yy >= 0 && yy < H && xx >= 0 && xx < W)
                    v = inbase[ci * HW + yy * W + xx];
            }
            Bs[kk][lcol] = v;
        }
        __syncthreads();
        #pragma unroll
        for (int kk = 0; kk < 8; kk++) {
            float a[8], b[8];
            #pragma unroll
            for (int i = 0; i < 8; i++) a[i] = As[kk][tm0 + i];
            #pragma unroll
            for (int j = 0; j < 8; j++) b[j] = Bs[kk][tn0 + j];
            #pragma unroll
            for (int i = 0; i < 8; i++)
                #pragma unroll
                for (int j = 0; j < 8; j++)
                    acc[i][j] = fmaf(a[i], b[j], acc[i][j]);
        }
        __syncthreads();
    }

    const float alpha_a = __ldg(&alphas[0]);
    const float s_w     = scale_p[1];
    const double F = (15.0 / (double)alpha_a) / (double)s_w;

    #pragma unroll
    for (int i = 0; i < 8; i++) {
        int m = tm0 + i;
        if (m >= COUT) continue;
        #pragma unroll
        for (int j = 0; j < 8; j++) {
            int jj = bx * 128 + tn0 + j;
            int n2 = jj / HW;
            int rm = jj - n2 * HW;
            int yy = rm >> 5, xx = rm & 31;
            double td = (double)acc[i][j] * F;
            float tq = (float)rint(td);
            tq = fminf(fmaxf(tq, 0.f), 15.f);
            out[(((size_t)n2 * H + yy) * W + xx) * COUT + m] = (uint8_t)tq;
        }
    }
}

// ----------------------------------------------------------------------------
// IMMA conv with fragment-ordered weights + 16B cp.async staging.
// Block: 128 rows(Cout, padded to COUTP) x NBLK pixels, 256 threads.
// Warp grid WM x WN; warp tile (128/WM) x (NBLK/WN).
// ----------------------------------------------------------------------------
template<int NBLK, int WM, int WN>
__global__ __launch_bounds__(256) void conv_frag_kernel(
    const uint8_t* __restrict__ in, const int* __restrict__ wfrag,
    uint8_t* __restrict__ out, int CIN, int COUT, int H, int sh, int COUTP,
    const float* __restrict__ alphas, const float* __restrict__ scale_p, int layer)
{
    constexpr int WROWS = 128 / WM;
    constexpr int AM = WROWS / 16;
    constexpr int NW = NBLK / WN;
    constexpr int AN = NW / 8;

    const int W = H, HW = H * H;
    const int K4 = (CIN * 9) >> 2;
    const int KT = K4 >> 3;
    const int cmask = (1 << sh) - 1;
    const int nrb = COUTP >> 4;

    __shared__ int      Asm[2][8 * 128];      // fragment-ordered A stage (4KB each)
    __shared__ unsigned Bsm[2][NBLK * 12];    // 12 words/pixel (8 data + pad)

    const int t = threadIdx.x;
    const int bx = blockIdx.x, by = blockIdx.y;
    const int lane = t & 31;
    const int wid  = t >> 5;
    const int gid  = lane >> 2;
    const int tig  = lane & 3;
    const int warp_m = wid / WN;
    const int warp_n = wid - warp_m * WN;

    // Hoisted per-thread B decode (thread owns pixel bpl, half bh)
    const int bpl = t >> 1, bh = t & 1;
    const bool bactive = (bpl < NBLK);
    int bn = 0, byy = 0, bxx = 0;
    if (bactive) {
        int jcol = bx * NBLK + bpl;
        bn = jcol / HW;
        int rem = jcol - bn * HW;
        byy = rem / W;
        bxx = rem - byy * W;
    }
    // Hoisted A stage addressing (thread owns rblk arblk, lane alane)
    const int arblk = t >> 5, alane = t & 31;
    const long abase = ((long)(by * 8 + arblk)) * 128 + alane * 4;

    uint32_t sA[2], sB[2];
    sA[0] = (uint32_t)__cvta_generic_to_shared(&Asm[0][0]);
    sA[1] = (uint32_t)__cvta_generic_to_shared(&Asm[1][0]);
    sB[0] = (uint32_t)__cvta_generic_to_shared(&Bsm[0][0]);
    sB[1] = (uint32_t)__cvta_generic_to_shared(&Bsm[1][0]);

    int c[AM][AN][4];
    #pragma unroll
    for (int am = 0; am < AM; am++)
        #pragma unroll
        for (int an = 0; an < AN; an++)
            #pragma unroll
            for (int q = 0; q < 4; q++) c[am][an][q] = 0;

    auto load_stage = [&](int kt, int buf) {
        // A: one 16B cp.async per thread (fully coalesced, zero-padded in pack)
        const int* ga = wfrag + (long)kt * nrb * 128 + abase;
        cp16(sA[buf] + (uint32_t)(arblk * 128 + alane * 4) * 4, ga, 16);
        // B: one 16B cp.async per thread (contiguous channel segment)
        if (bactive) {
            int kg0 = kt * 8;
            int rs = kg0 >> sh;
            int ci = ((kg0 & cmask) << 2) + bh * 16;
            int r = rs / 3, s2 = rs - r * 3;
            int yy = byy + r - 1;
            int xx = bxx + s2 - 1;
            bool ok = (yy >= 0 && yy < H && xx >= 0 && xx < W);
            const void* g = ok ? (const void*)(in + ((size_t)bn * HW + (size_t)yy * W + xx) * CIN + ci)
                               : (const void*)in;
            cp16(sB[buf] + (uint32_t)(bpl * 12 + bh * 4) * 4, g, ok ? 16u : 0u);
        }
        cp_commit();
    };

    load_stage(0, 0);

    for (int kt = 0; kt < KT; ++kt) {
        const int buf = kt & 1;
        cp_wait0();
        __syncthreads();
        if (kt + 1 < KT) load_stage(kt + 1, buf ^ 1);

        // A fragments: one LDS.128 per atom
        int a[AM][4];
        #pragma unroll
        for (int am = 0; am < AM; am++) {
            const int4 v = *reinterpret_cast<const int4*>(
                &Asm[buf][(warp_m * AM + am) * 128 + lane * 4]);
            a[am][0] = v.x; a[am][1] = v.y; a[am][2] = v.z; a[am][3] = v.w;
        }
        // B fragments: stride-12 rows are conflict-free for this pattern
        unsigned b[AN][2];
        #pragma unroll
        for (int an = 0; an < AN; an++) {
            int pix = warp_n * NW + an * 8 + gid;
            b[an][0] = Bsm[buf][pix * 12 + tig];
            b[an][1] = Bsm[buf][pix * 12 + tig + 4];
        }
        #pragma unroll
        for (int am = 0; am < AM; am++)
            #pragma unroll
            for (int an = 0; an < AN; an++)
                imma16832(c[am][an], a[am], b[an]);
        __syncthreads();
    }

    // Epilogue: exact quant via fp64 factor
    const float alpha_a = __ldg(&alphas[layer]);
    const float s_w     = scale_p[2 * layer + 1];
    const float alpha_p = __ldg(&alphas[layer - 1]);
    const double F = (15.0 / (double)alpha_a) / ((double)s_w * (15.0 / (double)alpha_p));

    #pragma unroll
    for (int am = 0; am < AM; am++) {
        int row0 = by * 128 + warp_m * WROWS + am * 16 + gid;
        #pragma unroll
        for (int an = 0; an < AN; an++) {
            int colb = bx * NBLK + warp_n * NW + an * 8 + 2 * tig;
            #pragma unroll
            for (int q = 0; q < 4; q++) {
                int row = row0 + (q >> 1) * 8;
                int col = colb + (q & 1);
                if (row >= COUT) continue;
                int n2 = col / HW;
                int rm = col - n2 * HW;
                int yy = rm / W, xx = rm - yy * W;
                double td = (double)c[am][an][q] * F;
                float tq = (float)rint(td);
                tq = fminf(fmaxf(tq, 0.f), 15.f);
                out[(((size_t)n2 * H + yy) * W + xx) * COUT + row] = (uint8_t)tq;
            }
        }
    }
}

// ----------------------------------------------------------------------------
// Pools (unchanged)
// ----------------------------------------------------------------------------
__global__ void pool8_kernel(const uint8_t* __restrict__ in, uint8_t* __restrict__ out,
                             int C, int Hin) {
    int Hout = Hin >> 1;
    int total = BATCH * Hout * Hout * C;
    int idx = blockIdx.x * blockDim.x + threadIdx.x;
    if (idx >= total) return;
    int c = idx % C;
    int tmp = idx / C;
    int x = tmp % Hout;
    tmp /= Hout;
    int y = tmp % Hout;
    int n = tmp / Hout;
    const uint8_t* p = in + (((size_t)n * Hin + 2 * y) * Hin + 2 * x) * C + c;
    size_t rows = (size_t)Hin * C;
    uint8_t v0 = p[0], v1 = p[C], v2 = p[rows], v3 = p[rows + C];
    uint8_t v = v0 > v1 ? v0 : v1;
    uint8_t w = v2 > v3 ? v2 : v3;
    out[idx] = v > w ? v : w;
}

__global__ void pool_final_kernel(const uint8_t* __restrict__ in, float* __restrict__ out,
                                  const float* __restrict__ alphas) {
    int total = BATCH * 512;
    int idx = blockIdx.x * blockDim.x + threadIdx.x;
    if (idx >= total) return;
    int c = idx & 511;
    int n = idx >> 9;
    const uint8_t* p = in + (size_t)n * 4 * 512 + c;
    uint8_t v0 = p[0], v1 = p[512], v2 = p[1024], v3 = p[1536];
    uint8_t v = v0 > v1 ? v0 : v1;
    uint8_t w = v2 > v3 ? v2 : v3;
    uint8_t m = v > w ? v : w;
    float sc = __fdiv_rn(15.0f, __ldg(&alphas[12]));
    out[idx] = __fdiv_rn((float)m, sc);
}

// ----------------------------------------------------------------------------
// FC: 64x64 block tile, 4x4 per thread. K summed in the SAME sequential order
// as before (fmaf chain, kt chunks ascending) -> bitwise-identical logits.
// ----------------------------------------------------------------------------
__global__ __launch_bounds__(256) void fc64_kernel(
    const float* __restrict__ act, const float* __restrict__ w,
    const float* __restrict__ bias, float* __restrict__ out,
    int M, int N, int K, int dorelu)
{
    __shared__ float As[16][68];
    __shared__ float Ws[16][68];
    const int t  = threadIdx.x;
    const int tx = t & 15, ty = t >> 4;
    const int mb = blockIdx.y * 64, nb = blockIdx.x * 64;

    float acc[4][4];
    #pragma unroll
    for (int i = 0; i < 4; i++)
        #pragma unroll
        for (int j = 0; j < 4; j++) acc[i][j] = 0.f;

    for (int kt = 0; kt < K; kt += 16) {
        #pragma unroll
        for (int u = 0; u < 4; u++) {
            int idx = t * 4 + u;           // 0..1023
            int mm = idx >> 4, kk = idx & 15;
            As[kk][mm] = (mb + mm < M) ? act[(size_t)(mb + mm) * K + kt + kk] : 0.f;
            Ws[kk][mm] = (nb + mm < N) ? w[(size_t)(nb + mm) * K + kt + kk] : 0.f;
        }
        __syncthreads();
        #pragma unroll
        for (int kk = 0; kk < 16; kk++) {
            float av[4], bv[4];
            #pragma unroll
            for (int i = 0; i < 4; i++) av[i] = As[kk][ty * 4 + i];
            #pragma unroll
            for (int j = 0; j < 4; j++) bv[j] = Ws[kk][tx * 4 + j];
            #pragma unroll
            for (int i = 0; i < 4; i++)
                #pragma unroll
                for (int j = 0; j < 4; j++)
                    acc[i][j] = fmaf(av[i], bv[j], acc[i][j]);
        }
        __syncthreads();
    }

    #pragma unroll
    for (int i = 0; i < 4; i++) {
        int row = mb + ty * 4 + i;
        if (row >= M) continue;
        #pragma unroll
        for (int j = 0; j < 4; j++) {
            int col = nb + tx * 4 + j;
            if (col >= N) continue;
            float v = acc[i][j] + bias[col];
            if (dorelu) v = fmaxf(v, 0.f);
            out[(size_t)row * N + col] = v;
        }
    }
}

// ----------------------------------------------------------------------------
// Host orchestration
// ----------------------------------------------------------------------------
struct LayerCfg { int cin, cout, h; bool pool_after; };
static const LayerCfg g_layers[NLAYERS] = {
    {  3,  64, 32, false},
    { 64,  64, 32, true },
    { 64, 128, 16, false},
    {128, 128, 16, true },
    {128, 256,  8, false},
    {256, 256,  8, false},
    {256, 256,  8, true },
    {256, 512,  4, false},
    {512, 512,  4, false},
    {512, 512,  4, true },
    {512, 512,  2, false},
    {512, 512,  2, false},
    {512, 512,  2, true },
};

static int ilog2i(int v) { int r = 0; while ((1 << r) < v) r++; return r; }

extern "C" void kernel_launch(void* const* d_in, const int* in_sizes, int n_in,
                              void* d_out, int out_size) {
    (void)in_sizes; (void)n_in; (void)out_size;

    const float* x      = (const float*)d_in[0];
    const float* convw[NLAYERS];
    for (int i = 0; i < NLAYERS; i++) convw[i] = (const float*)d_in[1 + i];
    const float* alphas = (const float*)d_in[14];
    const float* fc1_w  = (const float*)d_in[15];
    const float* fc1_b  = (const float*)d_in[16];
    const float* fc2_w  = (const float*)d_in[17];
    const float* fc2_b  = (const float*)d_in[18];
    const float* fc3_w  = (const float*)d_in[19];
    const float* fc3_b  = (const float*)d_in[20];

    uint8_t *a8A, *a8B;
    float *fc0, *fcA, *fcB, *wq0, *scale;
    int *wq8;
    double *partial;
    cudaGetSymbolAddress((void**)&a8A,     g_act8A);
    cudaGetSymbolAddress((void**)&a8B,     g_act8B);
    cudaGetSymbolAddress((void**)&fc0,     g_fc0);
    cudaGetSymbolAddress((void**)&fcA,     g_fcA);
    cudaGetSymbolAddress((void**)&fcB,     g_fcB);
    cudaGetSymbolAddress((void**)&wq0,     g_wq0);
    cudaGetSymbolAddress((void**)&wq8,     g_wq8);
    cudaGetSymbolAddress((void**)&partial, g_partial);
    cudaGetSymbolAddress((void**)&scale,   g_scale);

    // Per-layer fragment-pack geometry (layers 1..12 -> index 0..11)
    PackArgs pa;
    long acc_off = 0;
    int max_pack_blocks = 1;
    for (int i = 1; i < NLAYERS; i++) {
        int li = i - 1;
        int CIN = g_layers[i].cin, COUT = g_layers[i].cout;
        int COUTP = ((COUT + 127) / 128) * 128;
        int K4 = (CIN * 9) >> 2;
        int KT = K4 >> 3;
        int nwords = KT * (COUTP >> 4) * 128;
        pa.w[li]      = convw[i];
        pa.off[li]    = acc_off;
        pa.cin[li]    = CIN;
        pa.cout[li]   = COUT;
        pa.coutp[li]  = COUTP;
        pa.sh[li]     = ilog2i(CIN >> 2);
        pa.nwords[li] = nwords;
        acc_off += nwords;
        int blks = (nwords + 255) / 256;
        if (blks > max_pack_blocks) max_pack_blocks = blks;
    }

    AbsArgs aa;
    for (int i = 0; i < NLAYERS; i++) {
        aa.p[i] = convw[i];
        aa.n[i] = g_layers[i].cout * g_layers[i].cin * 9;
    }

    // Prep: 3 fused launches + layer0 weights
    absum_all_kernel<<<dim3(256, 13), 256>>>(aa, partial);
    finalize_all_kernel<<<13, 256>>>(aa, partial, scale);
    quantw0_kernel<<<(27 * 64 + 255) / 256, 256>>>(convw[0], 27 * 64, 27, 64, scale, wq0);
    pack_frag_kernel<<<dim3(max_pack_blocks, 12), 256>>>(pa, scale, wq8);

    // Layer 0
    {
        int N = BATCH * 32 * 32;
        conv0_kernel<<<dim3(N / 128, 1), 256>>>(x, wq0, a8A, alphas, scale);
    }

    uint8_t* buf[2] = {a8A, a8B};
    int cur = 0;

    for (int i = 1; i < NLAYERS; i++) {
        const LayerCfg& L = g_layers[i];
        int li = i - 1;
        int N = BATCH * L.h * L.h;
        int dst = 1 - cur;
        int sh = pa.sh[li];
        int COUTP = pa.coutp[li];
        int gy = COUTP / 128;
        if ((N / 128) * gy >= 120) {
            dim3 grid(N / 128, gy);
            conv_frag_kernel<128, 2, 4><<<grid, 256>>>(buf[cur], wq8 + pa.off[li], buf[dst],
                                                       L.cin, L.cout, L.h, sh, COUTP,
                                                       alphas, scale, i);
        } else {
            dim3 grid(N / 64, gy);
            conv_frag_kernel<64, 4, 2><<<grid, 256>>>(buf[cur], wq8 + pa.off[li], buf[dst],
                                                      L.cin, L.cout, L.h, sh, COUTP,
                                                      alphas, scale, i);
        }
        cur = dst;
        if (L.pool_after) {
            if (i == NLAYERS - 1) {
                pool_final_kernel<<<(BATCH * 512 + 255) / 256, 256>>>(buf[cur], fc0, alphas);
            } else {
                int dst2 = 1 - cur;
                int Hout = L.h >> 1;
                int total = BATCH * Hout * Hout * L.cout;
                pool8_kernel<<<(total + 255) / 256, 256>>>(buf[cur], buf[dst2], L.cout, L.h);
                cur = dst2;
            }
        }
    }

    // FC head
    {
        dim3 grid1(512 / 64, BATCH / 64);
        fc64_kernel<<<grid1, 256>>>(fc0, fc1_w, fc1_b, fcA, BATCH, 512, 512, 1);
        fc64_kernel<<<grid1, 256>>>(fcA, fc2_w, fc2_b, fcB, BATCH, 512, 512, 1);
        dim3 grid3(1, BATCH / 64);
        fc64_kernel<<<grid3, 256>>>(fcB, fc3_w, fc3_b, (float*)d_out, BATCH, 10, 512, 0);
    }
}

// round 11
// speedup vs baseline: 11.2196x; 1.4038x over previous
#include <cuda_runtime.h>
#include <cstdint>

// ============================================================================
// Quantized VGG forward (batch 512) — integer levels end-to-end.
// Convs 1-12: IMMA m16n8k32 (s8 x u8 -> s32, exact), fragment-ordered weights,
// K-chunk 64 (16 packed words) per stage, warp tiles up to 64x64.
// Epilogue quant via fp64 factor (bit-exact decisions -> rel_err 0.0).
// ============================================================================

#define BATCH 512
#define NLAYERS 13

#define ACT8_ELEMS (512*64*32*32)
#define WQ8_WORDS  4000000

__device__ __align__(256) uint8_t g_act8A[ACT8_ELEMS];
__device__ __align__(256) uint8_t g_act8B[ACT8_ELEMS];
__device__ float   g_fc0[BATCH * 512];
__device__ float   g_fcA[BATCH * 512];
__device__ float   g_fcB[BATCH * 512];
__device__ float   g_wq0[27 * 64];
__device__ __align__(256) int g_wq8[WQ8_WORDS];   // fragment-ordered packed s8
__device__ double  g_partial[NLAYERS * 256];
__device__ float   g_scale[NLAYERS * 2];

struct AbsArgs  { const float* p[13]; int n[13]; };
struct PackArgs { const float* w[12]; long off[12]; int cin[12]; int cout[12];
                  int coutp[12]; int sh[12]; int nwords[12]; };

// ----------------------------------------------------------------------------
// asm helpers
// ----------------------------------------------------------------------------
__device__ __forceinline__ void cp16(uint32_t saddr, const void* g, unsigned sz) {
    asm volatile("cp.async.cg.shared.global [%0], [%1], 16, %2;"
                 :: "r"(saddr), "l"(g), "r"(sz) : "memory");
}
__device__ __forceinline__ void cp_commit() {
    asm volatile("cp.async.commit_group;" ::: "memory");
}
__device__ __forceinline__ void cp_wait0() {
    asm volatile("cp.async.wait_group 0;" ::: "memory");
}
__device__ __forceinline__ void imma16832(int* c, const int* a, const unsigned* b) {
    asm volatile(
        "mma.sync.aligned.m16n8k32.row.col.s32.s8.u8.s32 "
        "{%0,%1,%2,%3}, {%4,%5,%6,%7}, {%8,%9}, {%0,%1,%2,%3};"
        : "+r"(c[0]), "+r"(c[1]), "+r"(c[2]), "+r"(c[3])
        : "r"(a[0]), "r"(a[1]), "r"(a[2]), "r"(a[3]),
          "r"(b[0]), "r"(b[1]));
}

// ----------------------------------------------------------------------------
// Fused prep (identical reduction order -> same scale bits as R6-R10)
// ----------------------------------------------------------------------------
__global__ void absum_all_kernel(AbsArgs aa, double* __restrict__ partial) {
    int layer = blockIdx.y;
    const float* w = aa.p[layer];
    int n = aa.n[layer];
    __shared__ double s[256];
    double acc = 0.0;
    for (int i = blockIdx.x * 256 + threadIdx.x; i < n; i += 256 * 256)
        acc += (double)fabsf(w[i]);
    s[threadIdx.x] = acc;
    __syncthreads();
    for (int o = 128; o > 0; o >>= 1) {
        if (threadIdx.x < o) s[threadIdx.x] += s[threadIdx.x + o];
        __syncthreads();
    }
    if (threadIdx.x == 0) partial[layer * 256 + blockIdx.x] = s[0];
}

__global__ void finalize_all_kernel(AbsArgs aa, const double* __restrict__ partial,
                                    float* __restrict__ scale_out) {
    int layer = blockIdx.x;
    __shared__ double s[256];
    s[threadIdx.x] = partial[layer * 256 + threadIdx.x];
    __syncthreads();
    for (int o = 128; o > 0; o >>= 1) {
        if (threadIdx.x < o) s[threadIdx.x] += s[threadIdx.x + o];
        __syncthreads();
    }
    if (threadIdx.x == 0) {
        float sum_f = (float)s[0];
        float mean  = __fdiv_rn(sum_f, (float)aa.n[layer]);
        float alpha = 2.0f * mean;
        float sw    = __fdiv_rn(7.0f, alpha);
        scale_out[layer * 2 + 0] = alpha;
        scale_out[layer * 2 + 1] = sw;
    }
}

__global__ void quantw0_kernel(const float* __restrict__ w, int n, int K, int Cout,
                               const float* __restrict__ scale_p, float* __restrict__ wq_t) {
    int idx = blockIdx.x * blockDim.x + threadIdx.x;
    if (idx >= n) return;
    float alpha = scale_p[0];
    float s     = scale_p[1];
    float wc = fminf(fmaxf(w[idx], -alpha), alpha);
    float m  = rintf(wc * s);
    int mo = idx / K;
    int k  = idx - mo * K;
    wq_t[k * Cout + mo] = m;
}

// Fragment-ordered pack (layout identical to R10: [kt8][nrb][128])
__global__ void pack_frag_kernel(PackArgs pa, const float* __restrict__ scale,
                                 int* __restrict__ wq8) {
    int layer = blockIdx.y;
    int nw = pa.nwords[layer];
    int idx = blockIdx.x * 256 + threadIdx.x;
    if (idx >= nw) return;
    int q    = idx & 3;
    int lane = (idx >> 2) & 31;
    int blk  = idx >> 7;
    int nrb  = pa.coutp[layer] >> 4;
    int kt   = blk / nrb;
    int rblk = blk - kt * nrb;
    int gid = lane >> 2, tig = lane & 3;
    int row = rblk * 16 + ((q & 1) << 3) + gid;
    int k4  = kt * 8 + ((q >> 1) << 2) + tig;
    int val = 0;
    int COUT = pa.cout[layer];
    if (row < COUT) {
        int CIN = pa.cin[layer];
        int sh = pa.sh[layer];
        int cmask = (1 << sh) - 1;
        int rs = k4 >> sh;
        int ci0 = (k4 & cmask) << 2;
        int r = rs / 3, s2 = rs - r * 3;
        float alpha = scale[(layer + 1) * 2 + 0];
        float s     = scale[(layer + 1) * 2 + 1];
        const float* w = pa.w[layer];
        unsigned pack = 0;
        #pragma unroll
        for (int t = 0; t < 4; t++) {
            int ci = ci0 + t;
            float v = w[((row * CIN + ci) * 3 + r) * 3 + s2];
            float wc = fminf(fmaxf(v, -alpha), alpha);
            int mi = (int)rintf(wc * s);
            pack |= ((unsigned)(mi & 0xFF)) << (8 * t);
        }
        val = (int)pack;
    }
    wq8[pa.off[layer] + idx] = val;
}

// ----------------------------------------------------------------------------
// Layer 0 conv: fp32 GEMM (K=27) -> u8 NHWC (unchanged, verified)
// ----------------------------------------------------------------------------
__global__ __launch_bounds__(256) void conv0_kernel(
    const float* __restrict__ x, const float* __restrict__ wq_t,
    uint8_t* __restrict__ out,
    const float* __restrict__ alphas, const float* __restrict__ scale_p)
{
    const int CIN = 3, COUT = 64, H = 32, W = 32, HW = 1024;
    const int K = 27;

    __shared__ float As[8][128];
    __shared__ float Bs[8][128];

    const int t = threadIdx.x;
    const int bx = blockIdx.x;

    const int lcol = t & 127;
    const int kl   = t >> 7;
    const int jcol = bx * 128 + lcol;
    int n_ = jcol >> 10;
    int rem = jcol & 1023;
    int y_ = rem >> 5;
    int x_ = rem & 31;
    const float* inbase = x + (size_t)n_ * CIN * HW;

    const int arow = lcol;
    const bool avalid = (arow < COUT);

    float acc[8][8];
    #pragma unroll
    for (int i = 0; i < 8; i++)
        #pragma unroll
        for (int j = 0; j < 8; j++) acc[i][j] = 0.f;

    const int tm0 = (t & 15) * 8;
    const int tn0 = (t >> 4) * 8;

    for (int kt = 0; kt < 4; ++kt) {
        const int kbase = kt * 8;
        #pragma unroll
        for (int i = 0; i < 4; i++) {
            int kk = kl + 2 * i;
            int kg = kbase + kk;
            float v = 0.f;
            if (avalid && kg < K) v = wq_t[kg * COUT + arow];
            As[kk][lcol] = v;
        }
        #pragma unroll
        for (int i = 0; i < 4; i++) {
            int kk = kl + 2 * i;
            int kg = kbase + kk;
            float v = 0.f;
            if (kg < K) {
                int ci = kg / 9;
                int rs = kg - ci * 9;
                int r = rs / 3;
                int s2 = rs - r * 3;
                int yy = y_ + r - 1;
                int xx = x_ + s2 - 1;
                if (yy >= 0 && yy < H && xx >= 0 && xx < W)
                    v = inbase[ci * HW + yy * W + xx];
            }
            Bs[kk][lcol] = v;
        }
        __syncthreads();
        #pragma unroll
        for (int kk = 0; kk < 8; kk++) {
            float a[8], b[8];
            #pragma unroll
            for (int i = 0; i < 8; i++) a[i] = As[kk][tm0 + i];
            #pragma unroll
            for (int j = 0; j < 8; j++) b[j] = Bs[kk][tn0 + j];
            #pragma unroll
            for (int i = 0; i < 8; i++)
                #pragma unroll
                for (int j = 0; j < 8; j++)
                    acc[i][j] = fmaf(a[i], b[j], acc[i][j]);
        }
        __syncthreads();
    }

    const float alpha_a = __ldg(&alphas[0]);
    const float s_w     = scale_p[1];
    const double F = (15.0 / (double)alpha_a) / (double)s_w;

    #pragma unroll
    for (int i = 0; i < 8; i++) {
        int m = tm0 + i;
        if (m >= COUT) continue;
        #pragma unroll
        for (int j = 0; j < 8; j++) {
            int jj = bx * 128 + tn0 + j;
            int n2 = jj >> 10;
            int rm = jj & 1023;
            int yy = rm >> 5, xx = rm & 31;
            double td = (double)acc[i][j] * F;
            float tq = (float)rint(td);
            tq = fminf(fmaxf(tq, 0.f), 15.f);
            out[(((size_t)n2 * H + yy) * W + xx) * COUT + m] = (uint8_t)tq;
        }
    }
}

// ----------------------------------------------------------------------------
// IMMA conv, K-chunk 16 packed words (=64 K), dynamic SMEM double buffer.
// Block: 128 rows x NBLK pixels, 256 threads, warp grid WM x WN.
// A stage: 2 kt8-blocks x 8 rblk x 128 words. B stage: NBLK x 20-word rows.
// ----------------------------------------------------------------------------
template<int NBLK, int WM, int WN>
__global__ __launch_bounds__(256) void conv_frag_kernel(
    const uint8_t* __restrict__ in, const int* __restrict__ wfrag,
    uint8_t* __restrict__ out, int CIN, int COUT, int H, int sh, int COUTP,
    int hwsh, int wsh,
    const float* __restrict__ alphas, const float* __restrict__ scale_p, int layer)
{
    constexpr int WROWS = 128 / WM;
    constexpr int AM = WROWS / 16;
    constexpr int NW = NBLK / WN;
    constexpr int AN = NW / 8;
    constexpr int TPP = 256 / NBLK;       // threads per pixel
    constexpr int QPT = 4 / TPP;          // 16B quarters per thread
    constexpr int ASTAGE = 2048;          // words per A buffer
    constexpr int BSTRIDE = 20;           // words per pixel row

    const int W = H, HW = H * H;
    const int hwmask = HW - 1, wmask = W - 1;
    const int K4 = (CIN * 9) >> 2;
    const int KT = K4 >> 4;               // K-chunks of 16 packed words
    const int cmask = (1 << sh) - 1;
    const int nrb = COUTP >> 4;

    extern __shared__ char smem[];
    int*      Asm = (int*)smem;                         // 2 x 2048 words
    unsigned* Bsm = (unsigned*)(smem + 2 * ASTAGE * 4); // 2 x NBLK*20 words

    const int t = threadIdx.x;
    const int bx = blockIdx.x, by = blockIdx.y;
    const int lane = t & 31;
    const int wid  = t >> 5;
    const int gid  = lane >> 2;
    const int tig  = lane & 3;
    const int warp_m = wid / WN;
    const int warp_n = wid - warp_m * WN;

    // B decode: thread owns pixel p, quarters qb..qb+QPT-1
    const int p  = t % NBLK;
    const int qb = (t / NBLK) * QPT;
    int bn, byy, bxx;
    {
        int jcol = bx * NBLK + p;
        bn  = jcol >> hwsh;
        int rem = jcol & hwmask;
        byy = rem >> wsh;
        bxx = rem & wmask;
    }
    // A stage addressing: thread t covers words t*4..t*4+3 in each kt8 half
    const int arblk = t >> 5;
    const int aoff  = (t & 31) * 4;

    uint32_t sAb = (uint32_t)__cvta_generic_to_shared(Asm);
    uint32_t sBb = (uint32_t)__cvta_generic_to_shared(Bsm);

    int c[AM][AN][4];
    #pragma unroll
    for (int am = 0; am < AM; am++)
        #pragma unroll
        for (int an = 0; an < AN; an++)
            #pragma unroll
            for (int q = 0; q < 4; q++) c[am][an][q] = 0;

    auto load_stage = [&](int kt2, int buf) {
        // A: 2 x 16B per thread
        #pragma unroll
        for (int h = 0; h < 2; h++) {
            const int* ga = wfrag + ((long)(kt2 * 2 + h) * nrb + by * 8 + arblk) * 128 + aoff;
            cp16(sAb + (uint32_t)(buf * ASTAGE + h * 1024 + t * 4) * 4, ga, 16);
        }
        // B: QPT x 16B per thread, contiguous 64B channel run per pixel
        int kg0 = kt2 * 16;
        int rs = kg0 >> sh;
        int ci0 = (kg0 & cmask) << 2;
        int r = rs / 3, s2 = rs - r * 3;
        int yy = byy + r - 1;
        int xx = bxx + s2 - 1;
        bool ok = (yy >= 0 && yy < H && xx >= 0 && xx < W);
        const uint8_t* gb = ok ? in + ((size_t)bn * HW + (size_t)yy * W + xx) * CIN + ci0
                               : in;
        #pragma unroll
        for (int j = 0; j < QPT; j++) {
            int q = qb + j;
            cp16(sBb + (uint32_t)(buf * NBLK * BSTRIDE + p * BSTRIDE + q * 4) * 4,
                 gb + q * 16, ok ? 16u : 0u);
        }
        cp_commit();
    };

    load_stage(0, 0);

    for (int kt2 = 0; kt2 < KT; ++kt2) {
        const int buf = kt2 & 1;
        cp_wait0();
        __syncthreads();
        if (kt2 + 1 < KT) load_stage(kt2 + 1, buf ^ 1);

        const int*      Ab = Asm + buf * ASTAGE;
        const unsigned* Bb = Bsm + buf * NBLK * BSTRIDE;

        #pragma unroll
        for (int h = 0; h < 2; h++) {
            int a[AM][4];
            #pragma unroll
            for (int am = 0; am < AM; am++) {
                const int4 v = *reinterpret_cast<const int4*>(
                    &Ab[h * 1024 + (warp_m * AM + am) * 128 + lane * 4]);
                a[am][0] = v.x; a[am][1] = v.y; a[am][2] = v.z; a[am][3] = v.w;
            }
            unsigned b[AN][2];
            #pragma unroll
            for (int an = 0; an < AN; an++) {
                int pix = warp_n * NW + an * 8 + gid;
                b[an][0] = Bb[pix * BSTRIDE + h * 8 + tig];
                b[an][1] = Bb[pix * BSTRIDE + h * 8 + tig + 4];
            }
            #pragma unroll
            for (int am = 0; am < AM; am++)
                #pragma unroll
                for (int an = 0; an < AN; an++)
                    imma16832(c[am][an], a[am], b[an]);
        }
        __syncthreads();
    }

    // Epilogue: exact quant via fp64 factor
    const float alpha_a = __ldg(&alphas[layer]);
    const float s_w     = scale_p[2 * layer + 1];
    const float alpha_p = __ldg(&alphas[layer - 1]);
    const double F = (15.0 / (double)alpha_a) / ((double)s_w * (15.0 / (double)alpha_p));

    #pragma unroll
    for (int am = 0; am < AM; am++) {
        int row0 = by * 128 + warp_m * WROWS + am * 16 + gid;
        #pragma unroll
        for (int an = 0; an < AN; an++) {
            int colb = bx * NBLK + warp_n * NW + an * 8 + 2 * tig;
            #pragma unroll
            for (int q = 0; q < 4; q++) {
                int row = row0 + (q >> 1) * 8;
                int col = colb + (q & 1);
                if (row >= COUT) continue;
                int n2 = col >> hwsh;
                int rm = col & hwmask;
                int yy = rm >> wsh, xx = rm & wmask;
                double td = (double)c[am][an][q] * F;
                float tq = (float)rint(td);
                tq = fminf(fmaxf(tq, 0.f), 15.f);
                out[(((size_t)n2 * H + yy) * W + xx) * COUT + row] = (uint8_t)tq;
            }
        }
    }
}

// ----------------------------------------------------------------------------
// Pools (unchanged)
// ----------------------------------------------------------------------------
__global__ void pool8_kernel(const uint8_t* __restrict__ in, uint8_t* __restrict__ out,
                             int C, int Hin) {
    int Hout = Hin >> 1;
    int total = BATCH * Hout * Hout * C;
    int idx = blockIdx.x * blockDim.x + threadIdx.x;
    if (idx >= total) return;
    int c = idx % C;
    int tmp = idx / C;
    int x = tmp % Hout;
    tmp /= Hout;
    int y = tmp % Hout;
    int n = tmp / Hout;
    const uint8_t* p = in + (((size_t)n * Hin + 2 * y) * Hin + 2 * x) * C + c;
    size_t rows = (size_t)Hin * C;
    uint8_t v0 = p[0], v1 = p[C], v2 = p[rows], v3 = p[rows + C];
    uint8_t v = v0 > v1 ? v0 : v1;
    uint8_t w = v2 > v3 ? v2 : v3;
    out[idx] = v > w ? v : w;
}

__global__ void pool_final_kernel(const uint8_t* __restrict__ in, float* __restrict__ out,
                                  const float* __restrict__ alphas) {
    int total = BATCH * 512;
    int idx = blockIdx.x * blockDim.x + threadIdx.x;
    if (idx >= total) return;
    int c = idx & 511;
    int n = idx >> 9;
    const uint8_t* p = in + (size_t)n * 4 * 512 + c;
    uint8_t v0 = p[0], v1 = p[512], v2 = p[1024], v3 = p[1536];
    uint8_t v = v0 > v1 ? v0 : v1;
    uint8_t w = v2 > v3 ? v2 : v3;
    uint8_t m = v > w ? v : w;
    float sc = __fdiv_rn(15.0f, __ldg(&alphas[12]));
    out[idx] = __fdiv_rn((float)m, sc);
}

// ----------------------------------------------------------------------------
// FC: 64x64 tile, 4x4 per thread (sequential k order -> bitwise-identical)
// ----------------------------------------------------------------------------
__global__ __launch_bounds__(256) void fc64_kernel(
    const float* __restrict__ act, const float* __restrict__ w,
    const float* __restrict__ bias, float* __restrict__ out,
    int M, int N, int K, int dorelu)
{
    __shared__ float As[16][68];
    __shared__ float Ws[16][68];
    const int t  = threadIdx.x;
    const int tx = t & 15, ty = t >> 4;
    const int mb = blockIdx.y * 64, nb = blockIdx.x * 64;

    float acc[4][4];
    #pragma unroll
    for (int i = 0; i < 4; i++)
        #pragma unroll
        for (int j = 0; j < 4; j++) acc[i][j] = 0.f;

    for (int kt = 0; kt < K; kt += 16) {
        #pragma unroll
        for (int u = 0; u < 4; u++) {
            int idx = t * 4 + u;
            int mm = idx >> 4, kk = idx & 15;
            As[kk][mm] = (mb + mm < M) ? act[(size_t)(mb + mm) * K + kt + kk] : 0.f;
            Ws[kk][mm] = (nb + mm < N) ? w[(size_t)(nb + mm) * K + kt + kk] : 0.f;
        }
        __syncthreads();
        #pragma unroll
        for (int kk = 0; kk < 16; kk++) {
            float av[4], bv[4];
            #pragma unroll
            for (int i = 0; i < 4; i++) av[i] = As[kk][ty * 4 + i];
            #pragma unroll
            for (int j = 0; j < 4; j++) bv[j] = Ws[kk][tx * 4 + j];
            #pragma unroll
            for (int i = 0; i < 4; i++)
                #pragma unroll
                for (int j = 0; j < 4; j++)
                    acc[i][j] = fmaf(av[i], bv[j], acc[i][j]);
        }
        __syncthreads();
    }

    #pragma unroll
    for (int i = 0; i < 4; i++) {
        int row = mb + ty * 4 + i;
        if (row >= M) continue;
        #pragma unroll
        for (int j = 0; j < 4; j++) {
            int col = nb + tx * 4 + j;
            if (col >= N) continue;
            float v = acc[i][j] + bias[col];
            if (dorelu) v = fmaxf(v, 0.f);
            out[(size_t)row * N + col] = v;
        }
    }
}

// ----------------------------------------------------------------------------
// Host orchestration
// ----------------------------------------------------------------------------
struct LayerCfg { int cin, cout, h; bool pool_after; };
static const LayerCfg g_layers[NLAYERS] = {
    {  3,  64, 32, false},
    { 64,  64, 32, true },
    { 64, 128, 16, false},
    {128, 128, 16, true },
    {128, 256,  8, false},
    {256, 256,  8, false},
    {256, 256,  8, true },
    {256, 512,  4, false},
    {512, 512,  4, false},
    {512, 512,  4, true },
    {512, 512,  2, false},
    {512, 512,  2, false},
    {512, 512,  2, true },
};

static int ilog2i(int v) { int r = 0; while ((1 << r) < v) r++; return r; }

extern "C" void kernel_launch(void* const* d_in, const int* in_sizes, int n_in,
                              void* d_out, int out_size) {
    (void)in_sizes; (void)n_in; (void)out_size;

    const float* x      = (const float*)d_in[0];
    const float* convw[NLAYERS];
    for (int i = 0; i < NLAYERS; i++) convw[i] = (const float*)d_in[1 + i];
    const float* alphas = (const float*)d_in[14];
    const float* fc1_w  = (const float*)d_in[15];
    const float* fc1_b  = (const float*)d_in[16];
    const float* fc2_w  = (const float*)d_in[17];
    const float* fc2_b  = (const float*)d_in[18];
    const float* fc3_w  = (const float*)d_in[19];
    const float* fc3_b  = (const float*)d_in[20];

    uint8_t *a8A, *a8B;
    float *fc0, *fcA, *fcB, *wq0, *scale;
    int *wq8;
    double *partial;
    cudaGetSymbolAddress((void**)&a8A,     g_act8A);
    cudaGetSymbolAddress((void**)&a8B,     g_act8B);
    cudaGetSymbolAddress((void**)&fc0,     g_fc0);
    cudaGetSymbolAddress((void**)&fcA,     g_fcA);
    cudaGetSymbolAddress((void**)&fcB,     g_fcB);
    cudaGetSymbolAddress((void**)&wq0,     g_wq0);
    cudaGetSymbolAddress((void**)&wq8,     g_wq8);
    cudaGetSymbolAddress((void**)&partial, g_partial);
    cudaGetSymbolAddress((void**)&scale,   g_scale);

    // Allow >48KB dynamic SMEM for the wide variant (idempotent host call)
    static bool attr_set = false;
    if (!attr_set) {
        cudaFuncSetAttribute(conv_frag_kernel<256, 2, 4>,
                             cudaFuncAttributeMaxDynamicSharedMemorySize, 64 * 1024);
        attr_set = true;
    }

    PackArgs pa;
    long acc_off = 0;
    int max_pack_blocks = 1;
    for (int i = 1; i < NLAYERS; i++) {
        int li = i - 1;
        int CIN = g_layers[i].cin, COUT = g_layers[i].cout;
        int COUTP = ((COUT + 127) / 128) * 128;
        int K4 = (CIN * 9) >> 2;
        int KT8 = K4 >> 3;
        int nwords = KT8 * (COUTP >> 4) * 128;
        pa.w[li]      = convw[i];
        pa.off[li]    = acc_off;
        pa.cin[li]    = CIN;
        pa.cout[li]   = COUT;
        pa.coutp[li]  = COUTP;
        pa.sh[li]     = ilog2i(CIN >> 2);
        pa.nwords[li] = nwords;
        acc_off += nwords;
        int blks = (nwords + 255) / 256;
        if (blks > max_pack_blocks) max_pack_blocks = blks;
    }

    AbsArgs aa;
    for (int i = 0; i < NLAYERS; i++) {
        aa.p[i] = convw[i];
        aa.n[i] = g_layers[i].cout * g_layers[i].cin * 9;
    }

    absum_all_kernel<<<dim3(256, 13), 256>>>(aa, partial);
    finalize_all_kernel<<<13, 256>>>(aa, partial, scale);
    quantw0_kernel<<<(27 * 64 + 255) / 256, 256>>>(convw[0], 27 * 64, 27, 64, scale, wq0);
    pack_frag_kernel<<<dim3(max_pack_blocks, 12), 256>>>(pa, scale, wq8);

    {
        int N = BATCH * 32 * 32;
        conv0_kernel<<<dim3(N / 128, 1), 256>>>(x, wq0, a8A, alphas, scale);
    }

    uint8_t* buf[2] = {a8A, a8B};
    int cur = 0;

    for (int i = 1; i < NLAYERS; i++) {
        const LayerCfg& L = g_layers[i];
        int li = i - 1;
        int N = BATCH * L.h * L.h;
        int dst = 1 - cur;
        int sh = pa.sh[li];
        int COUTP = pa.coutp[li];
        int gy = COUTP / 128;
        int hwsh = ilog2i(L.h * L.h);
        int wsh  = ilog2i(L.h);

        if (N >= 256 && (N / 256) * gy >= 148) {
            size_t smem = 2 * 2048 * 4 + 2 * 256 * 20 * 4;   // 57344
            dim3 grid(N / 256, gy);
            conv_frag_kernel<256, 2, 4><<<grid, 256, smem>>>(
                buf[cur], wq8 + pa.off[li], buf[dst],
                L.cin, L.cout, L.h, sh, COUTP, hwsh, wsh, alphas, scale, i);
        } else if (N >= 128 && (N / 128) * gy >= 148) {
            size_t smem = 2 * 2048 * 4 + 2 * 128 * 20 * 4;   // 36864
            dim3 grid(N / 128, gy);
            conv_frag_kernel<128, 2, 4><<<grid, 256, smem>>>(
                buf[cur], wq8 + pa.off[li], buf[dst],
                L.cin, L.cout, L.h, sh, COUTP, hwsh, wsh, alphas, scale, i);
        } else {
            size_t smem = 2 * 2048 * 4 + 2 * 64 * 20 * 4;    // 26624
            dim3 grid(N / 64, gy);
            conv_frag_kernel<64, 4, 2><<<grid, 256, smem>>>(
                buf[cur], wq8 + pa.off[li], buf[dst],
                L.cin, L.cout, L.h, sh, COUTP, hwsh, wsh, alphas, scale, i);
        }
        cur = dst;
        if (L.pool_after) {
            if (i == NLAYERS - 1) {
                pool_final_kernel<<<(BATCH * 512 + 255) / 256, 256>>>(buf[cur], fc0, alphas);
            } else {
                int dst2 = 1 - cur;
                int Hout = L.h >> 1;
                int total = BATCH * Hout * Hout * L.cout;
                pool8_kernel<<<(total + 255) / 256, 256>>>(buf[cur], buf[dst2], L.cout, L.h);
                cur = dst2;
            }
        }
    }

    {
        dim3 grid1(512 / 64, BATCH / 64);
        fc64_kernel<<<grid1, 256>>>(fc0, fc1_w, fc1_b, fcA, BATCH, 512, 512, 1);
        fc64_kernel<<<grid1, 256>>>(fcA, fc2_w, fc2_b, fcB, BATCH, 512, 512, 1);
        dim3 grid3(1, BATCH / 64);
        fc64_kernel<<<grid3, 256>>>(fcB, fc3_w, fc3_b, (float*)d_out, BATCH, 10, 512, 0);
    }
}

// round 13
// speedup vs baseline: 11.5649x; 1.0308x over previous
#include <cuda_runtime.h>
#include <cstdint>

// ============================================================================
// Quantized VGG forward (batch 512) — integer levels end-to-end.
// Convs 1-12: IMMA m16n8k32 (s8 x u8 -> s32, exact), fragment-ordered weights,
// K-chunk 64, warp tiles up to 64x64, channel-interleaved activations so B
// fragments load as LDS.64. Weight pack keeps LOGICAL k4 mapping (the storage
// interleave already restores logical order at fragment load).
// Epilogue quant via fp64 factor (exact -> rel_err 0.0).
// ============================================================================

#define BATCH 512
#define NLAYERS 13

#define ACT8_ELEMS (512*64*32*32)
#define WQ8_WORDS  4000000

__device__ __align__(256) uint8_t g_act8A[ACT8_ELEMS];
__device__ __align__(256) uint8_t g_act8B[ACT8_ELEMS];
__device__ float   g_fc0[BATCH * 512];
__device__ float   g_fcA[BATCH * 512];
__device__ float   g_fcB[BATCH * 512];
__device__ float   g_wq0[32 * 64];
__device__ __align__(256) int g_wq8[WQ8_WORDS];
__device__ double  g_partial[NLAYERS * 256];
__device__ float   g_scale[NLAYERS * 2];

struct AbsArgs  { const float* p[13]; int n[13]; };
struct PackArgs { const float* w[12]; long off[12]; int cin[12]; int cout[12];
                  int coutp[12]; int sh[12]; int nwords[12]; };

// Channel permutation: within each 32-channel group, logical word lw stored at
// position s(lw) = ((lw&3)<<1)|(lw>>2)  (storage order holds [0,4,1,5,2,6,3,7]).
__device__ __forceinline__ int sigma_ch(int c) {
    int lw = (c >> 2) & 7;
    int s  = ((lw & 3) << 1) | (lw >> 2);
    return (c & ~31) + s * 4 + (c & 3);
}

// ----------------------------------------------------------------------------
// asm helpers
// ----------------------------------------------------------------------------
__device__ __forceinline__ void cp16(uint32_t saddr, const void* g, unsigned sz) {
    asm volatile("cp.async.cg.shared.global [%0], [%1], 16, %2;"
                 :: "r"(saddr), "l"(g), "r"(sz) : "memory");
}
__device__ __forceinline__ void cp_commit() {
    asm volatile("cp.async.commit_group;" ::: "memory");
}
__device__ __forceinline__ void cp_wait0() {
    asm volatile("cp.async.wait_group 0;" ::: "memory");
}
__device__ __forceinline__ void imma16832(int* c, const int* a, const unsigned* b) {
    asm volatile(
        "mma.sync.aligned.m16n8k32.row.col.s32.s8.u8.s32 "
        "{%0,%1,%2,%3}, {%4,%5,%6,%7}, {%8,%9}, {%0,%1,%2,%3};"
        : "+r"(c[0]), "+r"(c[1]), "+r"(c[2]), "+r"(c[3])
        : "r"(a[0]), "r"(a[1]), "r"(a[2]), "r"(a[3]),
          "r"(b[0]), "r"(b[1]));
}

// ----------------------------------------------------------------------------
// Fused prep (identical reduction order -> same scale bits as R6-R11)
// ----------------------------------------------------------------------------
__global__ void absum_all_kernel(AbsArgs aa, double* __restrict__ partial) {
    int layer = blockIdx.y;
    const float* w = aa.p[layer];
    int n = aa.n[layer];
    __shared__ double s[256];
    double acc = 0.0;
    for (int i = blockIdx.x * 256 + threadIdx.x; i < n; i += 256 * 256)
        acc += (double)fabsf(w[i]);
    s[threadIdx.x] = acc;
    __syncthreads();
    for (int o = 128; o > 0; o >>= 1) {
        if (threadIdx.x < o) s[threadIdx.x] += s[threadIdx.x + o];
        __syncthreads();
    }
    if (threadIdx.x == 0) partial[layer * 256 + blockIdx.x] = s[0];
}

__global__ void finalize_all_kernel(AbsArgs aa, const double* __restrict__ partial,
                                    float* __restrict__ scale_out) {
    int layer = blockIdx.x;
    __shared__ double s[256];
    s[threadIdx.x] = partial[layer * 256 + threadIdx.x];
    __syncthreads();
    for (int o = 128; o > 0; o >>= 1) {
        if (threadIdx.x < o) s[threadIdx.x] += s[threadIdx.x + o];
        __syncthreads();
    }
    if (threadIdx.x == 0) {
        float sum_f = (float)s[0];
        float mean  = __fdiv_rn(sum_f, (float)aa.n[layer]);
        float alpha = 2.0f * mean;
        float sw    = __fdiv_rn(7.0f, alpha);
        scale_out[layer * 2 + 0] = alpha;
        scale_out[layer * 2 + 1] = sw;
    }
}

__global__ void quantw0_kernel(const float* __restrict__ w, int n, int K, int Cout,
                               const float* __restrict__ scale_p, float* __restrict__ wq_t) {
    int idx = blockIdx.x * blockDim.x + threadIdx.x;
    if (idx >= n) return;
    float alpha = scale_p[0];
    float s     = scale_p[1];
    float wc = fminf(fmaxf(w[idx], -alpha), alpha);
    float m  = rintf(wc * s);
    int mo = idx / K;
    int k  = idx - mo * K;
    wq_t[k * Cout + mo] = m;
}

// Fragment-ordered pack, LOGICAL k4 mapping (R11-verified). The activation
// storage interleave delivers logical words {tig, tig+4} at fragment load, so
// weights must be packed for exactly those logical channel words.
__global__ void pack_frag_kernel(PackArgs pa, const float* __restrict__ scale,
                                 int* __restrict__ wq8) {
    int layer = blockIdx.y;
    int nw = pa.nwords[layer];
    int idx = blockIdx.x * 256 + threadIdx.x;
    if (idx >= nw) return;
    int q    = idx & 3;
    int lane = (idx >> 2) & 31;
    int blk  = idx >> 7;
    int nrb  = pa.coutp[layer] >> 4;
    int kt   = blk / nrb;
    int rblk = blk - kt * nrb;
    int gid = lane >> 2, tig = lane & 3;
    int row = rblk * 16 + ((q & 1) << 3) + gid;
    int k4  = kt * 8 + ((q >> 1) << 2) + tig;       // logical channel-word
    int val = 0;
    int COUT = pa.cout[layer];
    if (row < COUT) {
        int CIN = pa.cin[layer];
        int sh = pa.sh[layer];
        int cmask = (1 << sh) - 1;
        int rs = k4 >> sh;
        int ci0 = (k4 & cmask) << 2;                // logical channel base
        int r = rs / 3, s2 = rs - r * 3;
        float alpha = scale[(layer + 1) * 2 + 0];
        float s     = scale[(layer + 1) * 2 + 1];
        const float* w = pa.w[layer];
        unsigned pack = 0;
        #pragma unroll
        for (int t = 0; t < 4; t++) {
            int ci = ci0 + t;
            float v = w[((row * CIN + ci) * 3 + r) * 3 + s2];
            float wc = fminf(fmaxf(v, -alpha), alpha);
            int mi = (int)rintf(wc * s);
            pack |= ((unsigned)(mi & 0xFF)) << (8 * t);
        }
        val = (int)pack;
    }
    wq8[pa.off[layer] + idx] = val;
}

// ----------------------------------------------------------------------------
// Layer 0 conv: fp32 GEMM (K=27), tile 64(Cout) x 256(pixels).
// Output u8 NHWC with sigma channel permutation.
// ----------------------------------------------------------------------------
__global__ __launch_bounds__(256) void conv0_kernel(
    const float* __restrict__ x, const float* __restrict__ wq_t,
    uint8_t* __restrict__ out,
    const float* __restrict__ alphas, const float* __restrict__ scale_p)
{
    const int CIN = 3, COUT = 64, H = 32, W = 32, HW = 1024;
    const int K = 27;

    __shared__ float As[8][64];
    __shared__ float Bs[8][256];

    const int t = threadIdx.x;
    const int bx = blockIdx.x;

    const int jcol0 = bx * 256 + t;
    const int n0 = jcol0 >> 10;
    const int rem0 = jcol0 & 1023;
    const int y0 = rem0 >> 5;
    const int x0 = rem0 & 31;
    const float* inbase = x + (size_t)n0 * CIN * HW;

    float acc[8][8];
    #pragma unroll
    for (int i = 0; i < 8; i++)
        #pragma unroll
        for (int j = 0; j < 8; j++) acc[i][j] = 0.f;

    const int tm0 = (t & 7) * 8;
    const int tn0 = (t >> 3) * 8;

    for (int kt = 0; kt < 4; ++kt) {
        const int kbase = kt * 8;
        #pragma unroll
        for (int u = 0; u < 2; u++) {
            int idx = t * 2 + u;
            int col = idx & 63;
            int kk  = idx >> 6;
            int kg = kbase + kk;
            As[kk][col] = (kg < K) ? wq_t[kg * COUT + col] : 0.f;
        }
        #pragma unroll
        for (int u = 0; u < 8; u++) {
            int kg = kbase + u;
            float v = 0.f;
            if (kg < K) {
                int ci = kg / 9;
                int rs = kg - ci * 9;
                int r = rs / 3;
                int s2 = rs - r * 3;
                int yy = y0 + r - 1;
                int xx = x0 + s2 - 1;
                if (yy >= 0 && yy < H && xx >= 0 && xx < W)
                    v = inbase[ci * HW + yy * W + xx];
            }
            Bs[u][t] = v;
        }
        __syncthreads();
        #pragma unroll
        for (int kk = 0; kk < 8; kk++) {
            float a[8], b[8];
            #pragma unroll
            for (int i = 0; i < 8; i++) a[i] = As[kk][tm0 + i];
            #pragma unroll
            for (int j = 0; j < 8; j++) b[j] = Bs[kk][tn0 + j];
            #pragma unroll
            for (int i = 0; i < 8; i++)
                #pragma unroll
                for (int j = 0; j < 8; j++)
                    acc[i][j] = fmaf(a[i], b[j], acc[i][j]);
        }
        __syncthreads();
    }

    const float alpha_a = __ldg(&alphas[0]);
    const float s_w     = scale_p[1];
    const double F = (15.0 / (double)alpha_a) / (double)s_w;

    #pragma unroll
    for (int i = 0; i < 8; i++) {
        int m = tm0 + i;
        int ms = sigma_ch(m);
        #pragma unroll
        for (int j = 0; j < 8; j++) {
            int jj = bx * 256 + tn0 + j;
            int n2 = jj >> 10;
            int rm = jj & 1023;
            int yy = rm >> 5, xx = rm & 31;
            double td = (double)acc[i][j] * F;
            float tq = (float)rint(td);
            tq = fminf(fmaxf(tq, 0.f), 15.f);
            out[(((size_t)n2 * H + yy) * W + xx) * COUT + ms] = (uint8_t)tq;
        }
    }
}

// ----------------------------------------------------------------------------
// IMMA conv, K-chunk 16 packed words, B fragments via LDS.64 (interleaved
// channel storage), B row stride 24 words (conflict-free).
// ----------------------------------------------------------------------------
template<int NBLK, int WM, int WN>
__global__ __launch_bounds__(256) void conv_frag_kernel(
    const uint8_t* __restrict__ in, const int* __restrict__ wfrag,
    uint8_t* __restrict__ out, int CIN, int COUT, int H, int sh, int COUTP,
    int hwsh, int wsh,
    const float* __restrict__ alphas, const float* __restrict__ scale_p, int layer)
{
    constexpr int WROWS = 128 / WM;
    constexpr int AM = WROWS / 16;
    constexpr int NW = NBLK / WN;
    constexpr int AN = NW / 8;
    constexpr int TPP = 256 / NBLK;
    constexpr int QPT = 4 / TPP;
    constexpr int ASTAGE = 2048;
    constexpr int BSTRIDE = 24;

    const int W = H, HW = H * H;
    const int hwmask = HW - 1, wmask = W - 1;
    const int K4 = (CIN * 9) >> 2;
    const int KT = K4 >> 4;
    const int cmask = (1 << sh) - 1;
    const int nrb = COUTP >> 4;

    extern __shared__ char smem[];
    int*      Asm = (int*)smem;
    unsigned* Bsm = (unsigned*)(smem + 2 * ASTAGE * 4);

    const int t = threadIdx.x;
    const int bx = blockIdx.x, by = blockIdx.y;
    const int lane = t & 31;
    const int wid  = t >> 5;
    const int gid  = lane >> 2;
    const int tig  = lane & 3;
    const int warp_m = wid / WN;
    const int warp_n = wid - warp_m * WN;

    const int p  = t % NBLK;
    const int qb = (t / NBLK) * QPT;
    int bn, byy, bxx;
    {
        int jcol = bx * NBLK + p;
        bn  = jcol >> hwsh;
        int rem = jcol & hwmask;
        byy = rem >> wsh;
        bxx = rem & wmask;
    }
    const int arblk = t >> 5;
    const int aoff  = (t & 31) * 4;

    uint32_t sAb = (uint32_t)__cvta_generic_to_shared(Asm);
    uint32_t sBb = (uint32_t)__cvta_generic_to_shared(Bsm);

    int c[AM][AN][4];
    #pragma unroll
    for (int am = 0; am < AM; am++)
        #pragma unroll
        for (int an = 0; an < AN; an++)
            #pragma unroll
            for (int q = 0; q < 4; q++) c[am][an][q] = 0;

    auto load_stage = [&](int kt2, int buf) {
        #pragma unroll
        for (int h = 0; h < 2; h++) {
            const int* ga = wfrag + ((long)(kt2 * 2 + h) * nrb + by * 8 + arblk) * 128 + aoff;
            cp16(sAb + (uint32_t)(buf * ASTAGE + h * 1024 + t * 4) * 4, ga, 16);
        }
        int kg0 = kt2 * 16;
        int rs = kg0 >> sh;
        int ci0 = (kg0 & cmask) << 2;
        int r = rs / 3, s2 = rs - r * 3;
        int yy = byy + r - 1;
        int xx = bxx + s2 - 1;
        bool ok = (yy >= 0 && yy < H && xx >= 0 && xx < W);
        const uint8_t* gb = ok ? in + ((size_t)bn * HW + (size_t)yy * W + xx) * CIN + ci0
                               : in;
        #pragma unroll
        for (int j = 0; j < QPT; j++) {
            int q = qb + j;
            cp16(sBb + (uint32_t)(buf * NBLK * BSTRIDE + p * BSTRIDE + q * 4) * 4,
                 gb + q * 16, ok ? 16u : 0u);
        }
        cp_commit();
    };

    load_stage(0, 0);

    for (int kt2 = 0; kt2 < KT; ++kt2) {
        const int buf = kt2 & 1;
        cp_wait0();
        __syncthreads();
        if (kt2 + 1 < KT) load_stage(kt2 + 1, buf ^ 1);

        const int*      Ab = Asm + buf * ASTAGE;
        const unsigned* Bb = Bsm + buf * NBLK * BSTRIDE;

        #pragma unroll
        for (int h = 0; h < 2; h++) {
            int a[AM][4];
            #pragma unroll
            for (int am = 0; am < AM; am++) {
                const int4 v = *reinterpret_cast<const int4*>(
                    &Ab[h * 1024 + (warp_m * AM + am) * 128 + lane * 4]);
                a[am][0] = v.x; a[am][1] = v.y; a[am][2] = v.z; a[am][3] = v.w;
            }
            unsigned b[AN][2];
            #pragma unroll
            for (int an = 0; an < AN; an++) {
                int pix = warp_n * NW + an * 8 + gid;
                const uint2 v = *reinterpret_cast<const uint2*>(
                    &Bb[pix * BSTRIDE + h * 8 + 2 * tig]);
                b[an][0] = v.x;    // logical word tig   (storage interleave)
                b[an][1] = v.y;    // logical word tig+4
            }
            #pragma unroll
            for (int am = 0; am < AM; am++)
                #pragma unroll
                for (int an = 0; an < AN; an++)
                    imma16832(c[am][an], a[am], b[an]);
        }
        __syncthreads();
    }

    const float alpha_a = __ldg(&alphas[layer]);
    const float s_w     = scale_p[2 * layer + 1];
    const float alpha_p = __ldg(&alphas[layer - 1]);
    const double F = (15.0 / (double)alpha_a) / ((double)s_w * (15.0 / (double)alpha_p));

    #pragma unroll
    for (int am = 0; am < AM; am++) {
        int row0 = by * 128 + warp_m * WROWS + am * 16 + gid;
        #pragma unroll
        for (int an = 0; an < AN; an++) {
            int colb = bx * NBLK + warp_n * NW + an * 8 + 2 * tig;
            #pragma unroll
            for (int q = 0; q < 4; q++) {
                int row = row0 + (q >> 1) * 8;
                int col = colb + (q & 1);
                if (row >= COUT) continue;
                int n2 = col >> hwsh;
                int rm = col & hwmask;
                int yy = rm >> wsh, xx = rm & wmask;
                double td = (double)c[am][an][q] * F;
                float tq = (float)rint(td);
                tq = fminf(fmaxf(tq, 0.f), 15.f);
                out[(((size_t)n2 * H + yy) * W + xx) * COUT + sigma_ch(row)] = (uint8_t)tq;
            }
        }
    }
}

// ----------------------------------------------------------------------------
// Pools (pool8 channel-passthrough commutes with sigma; pool_final unpermutes)
// ----------------------------------------------------------------------------
__global__ void pool8_kernel(const uint8_t* __restrict__ in, uint8_t* __restrict__ out,
                             int C, int Hin) {
    int Hout = Hin >> 1;
    int total = BATCH * Hout * Hout * C;
    int idx = blockIdx.x * blockDim.x + threadIdx.x;
    if (idx >= total) return;
    int c = idx % C;
    int tmp = idx / C;
    int x = tmp % Hout;
    tmp /= Hout;
    int y = tmp % Hout;
    int n = tmp / Hout;
    const uint8_t* p = in + (((size_t)n * Hin + 2 * y) * Hin + 2 * x) * C + c;
    size_t rows = (size_t)Hin * C;
    uint8_t v0 = p[0], v1 = p[C], v2 = p[rows], v3 = p[rows + C];
    uint8_t v = v0 > v1 ? v0 : v1;
    uint8_t w = v2 > v3 ? v2 : v3;
    out[idx] = v > w ? v : w;
}

__global__ void pool_final_kernel(const uint8_t* __restrict__ in, float* __restrict__ out,
                                  const float* __restrict__ alphas) {
    int total = BATCH * 512;
    int idx = blockIdx.x * blockDim.x + threadIdx.x;
    if (idx >= total) return;
    int c = idx & 511;               // logical channel for the FC head
    int n = idx >> 9;
    const uint8_t* p = in + (size_t)n * 4 * 512 + sigma_ch(c);
    uint8_t v0 = p[0], v1 = p[512], v2 = p[1024], v3 = p[1536];
    uint8_t v = v0 > v1 ? v0 : v1;
    uint8_t w = v2 > v3 ? v2 : v3;
    uint8_t m = v > w ? v : w;
    float sc = __fdiv_rn(15.0f, __ldg(&alphas[12]));
    out[idx] = __fdiv_rn((float)m, sc);
}

// ----------------------------------------------------------------------------
// FC: 64x64 tile, 4x4 per thread (sequential k order -> bitwise-identical)
// ----------------------------------------------------------------------------
__global__ __launch_bounds__(256) void fc64_kernel(
    const float* __restrict__ act, const float* __restrict__ w,
    const float* __restrict__ bias, float* __restrict__ out,
    int M, int N, int K, int dorelu)
{
    __shared__ float As[16][68];
    __shared__ float Ws[16][68];
    const int t  = threadIdx.x;
    const int tx = t & 15, ty = t >> 4;
    const int mb = blockIdx.y * 64, nb = blockIdx.x * 64;

    float acc[4][4];
    #pragma unroll
    for (int i = 0; i < 4; i++)
        #pragma unroll
        for (int j = 0; j < 4; j++) acc[i][j] = 0.f;

    for (int kt = 0; kt < K; kt += 16) {
        #pragma unroll
        for (int u = 0; u < 4; u++) {
            int idx = t * 4 + u;
            int mm = idx >> 4, kk = idx & 15;
            As[kk][mm] = (mb + mm < M) ? act[(size_t)(mb + mm) * K + kt + kk] : 0.f;
            Ws[kk][mm] = (nb + mm < N) ? w[(size_t)(nb + mm) * K + kt + kk] : 0.f;
        }
        __syncthreads();
        #pragma unroll
        for (int kk = 0; kk < 16; kk++) {
            float av[4], bv[4];
            #pragma unroll
            for (int i = 0; i < 4; i++) av[i] = As[kk][ty * 4 + i];
            #pragma unroll
            for (int j = 0; j < 4; j++) bv[j] = Ws[kk][tx * 4 + j];
            #pragma unroll
            for (int i = 0; i < 4; i++)
                #pragma unroll
                for (int j = 0; j < 4; j++)
                    acc[i][j] = fmaf(av[i], bv[j], acc[i][j]);
        }
        __syncthreads();
    }

    #pragma unroll
    for (int i = 0; i < 4; i++) {
        int row = mb + ty * 4 + i;
        if (row >= M) continue;
        #pragma unroll
        for (int j = 0; j < 4; j++) {
            int col = nb + tx * 4 + j;
            if (col >= N) continue;
            float v = acc[i][j] + bias[col];
            if (dorelu) v = fmaxf(v, 0.f);
            out[(size_t)row * N + col] = v;
        }
    }
}

// ----------------------------------------------------------------------------
// Host orchestration
// ----------------------------------------------------------------------------
struct LayerCfg { int cin, cout, h; bool pool_after; };
static const LayerCfg g_layers[NLAYERS] = {
    {  3,  64, 32, false},
    { 64,  64, 32, true },
    { 64, 128, 16, false},
    {128, 128, 16, true },
    {128, 256,  8, false},
    {256, 256,  8, false},
    {256, 256,  8, true },
    {256, 512,  4, false},
    {512, 512,  4, false},
    {512, 512,  4, true },
    {512, 512,  2, false},
    {512, 512,  2, false},
    {512, 512,  2, true },
};

static int ilog2i(int v) { int r = 0; while ((1 << r) < v) r++; return r; }

extern "C" void kernel_launch(void* const* d_in, const int* in_sizes, int n_in,
                              void* d_out, int out_size) {
    (void)in_sizes; (void)n_in; (void)out_size;

    const float* x      = (const float*)d_in[0];
    const float* convw[NLAYERS];
    for (int i = 0; i < NLAYERS; i++) convw[i] = (const float*)d_in[1 + i];
    const float* alphas = (const float*)d_in[14];
    const float* fc1_w  = (const float*)d_in[15];
    const float* fc1_b  = (const float*)d_in[16];
    const float* fc2_w  = (const float*)d_in[17];
    const float* fc2_b  = (const float*)d_in[18];
    const float* fc3_w  = (const float*)d_in[19];
    const float* fc3_b  = (const float*)d_in[20];

    uint8_t *a8A, *a8B;
    float *fc0, *fcA, *fcB, *wq0, *scale;
    int *wq8;
    double *partial;
    cudaGetSymbolAddress((void**)&a8A,     g_act8A);
    cudaGetSymbolAddress((void**)&a8B,     g_act8B);
    cudaGetSymbolAddress((void**)&fc0,     g_fc0);
    cudaGetSymbolAddress((void**)&fcA,     g_fcA);
    cudaGetSymbolAddress((void**)&fcB,     g_fcB);
    cudaGetSymbolAddress((void**)&wq0,     g_wq0);
    cudaGetSymbolAddress((void**)&wq8,     g_wq8);
    cudaGetSymbolAddress((void**)&partial, g_partial);
    cudaGetSymbolAddress((void**)&scale,   g_scale);

    static bool attr_set = false;
    if (!attr_set) {
        cudaFuncSetAttribute(conv_frag_kernel<256, 2, 4>,
                             cudaFuncAttributeMaxDynamicSharedMemorySize, 96 * 1024);
        attr_set = true;
    }

    PackArgs pa;
    long acc_off = 0;
    int max_pack_blocks = 1;
    for (int i = 1; i < NLAYERS; i++) {
        int li = i - 1;
        int CIN = g_layers[i].cin, COUT = g_layers[i].cout;
        int COUTP = ((COUT + 127) / 128) * 128;
        int K4 = (CIN * 9) >> 2;
        int KT8 = K4 >> 3;
        int nwords = KT8 * (COUTP >> 4) * 128;
        pa.w[li]      = convw[i];
        pa.off[li]    = acc_off;
        pa.cin[li]    = CIN;
        pa.cout[li]   = COUT;
        pa.coutp[li]  = COUTP;
        pa.sh[li]     = ilog2i(CIN >> 2);
        pa.nwords[li] = nwords;
        acc_off += nwords;
        int blks = (nwords + 255) / 256;
        if (blks > max_pack_blocks) max_pack_blocks = blks;
    }

    AbsArgs aa;
    for (int i = 0; i < NLAYERS; i++) {
        aa.p[i] = convw[i];
        aa.n[i] = g_layers[i].cout * g_layers[i].cin * 9;
    }

    absum_all_kernel<<<dim3(256, 13), 256>>>(aa, partial);
    finalize_all_kernel<<<13, 256>>>(aa, partial, scale);
    quantw0_kernel<<<(27 * 64 + 255) / 256, 256>>>(convw[0], 27 * 64, 27, 64, scale, wq0);
    pack_frag_kernel<<<dim3(max_pack_blocks, 12), 256>>>(pa, scale, wq8);

    {
        int N = BATCH * 32 * 32;
        conv0_kernel<<<dim3(N / 256, 1), 256>>>(x, wq0, a8A, alphas, scale);
    }

    uint8_t* buf[2] = {a8A, a8B};
    int cur = 0;

    for (int i = 1; i < NLAYERS; i++) {
        const LayerCfg& L = g_layers[i];
        int li = i - 1;
        int N = BATCH * L.h * L.h;
        int dst = 1 - cur;
        int sh = pa.sh[li];
        int COUTP = pa.coutp[li];
        int gy = COUTP / 128;
        int hwsh = ilog2i(L.h * L.h);
        int wsh  = ilog2i(L.h);

        if (N >= 256 && (N / 256) * gy >= 148) {
            size_t smem = 2 * 2048 * 4 + 2 * 256 * 24 * 4;   // 65536
            dim3 grid(N / 256, gy);
            conv_frag_kernel<256, 2, 4><<<grid, 256, smem>>>(
                buf[cur], wq8 + pa.off[li], buf[dst],
                L.cin, L.cout, L.h, sh, COUTP, hwsh, wsh, alphas, scale, i);
        } else if (N >= 128 && (N / 128) * gy >= 148) {
            size_t smem = 2 * 2048 * 4 + 2 * 128 * 24 * 4;   // 40960
            dim3 grid(N / 128, gy);
            conv_frag_kernel<128, 2, 4><<<grid, 256, smem>>>(
                buf[cur], wq8 + pa.off[li], buf[dst],
                L.cin, L.cout, L.h, sh, COUTP, hwsh, wsh, alphas, scale, i);
        } else {
            size_t smem = 2 * 2048 * 4 + 2 * 64 * 24 * 4;    // 28672
            dim3 grid(N / 64, gy);
            conv_frag_kernel<64, 4, 2><<<grid, 256, smem>>>(
                buf[cur], wq8 + pa.off[li], buf[dst],
                L.cin, L.cout, L.h, sh, COUTP, hwsh, wsh, alphas, scale, i);
        }
        cur = dst;
        if (L.pool_after) {
            if (i == NLAYERS - 1) {
                pool_final_kernel<<<(BATCH * 512 + 255) / 256, 256>>>(buf[cur], fc0, alphas);
            } else {
                int dst2 = 1 - cur;
                int Hout = L.h >> 1;
                int total = BATCH * Hout * Hout * L.cout;
                pool8_kernel<<<(total + 255) / 256, 256>>>(buf[cur], buf[dst2], L.cout, L.h);
                cur = dst2;
            }
        }
    }

    {
        dim3 grid1(512 / 64, BATCH / 64);
        fc64_kernel<<<grid1, 256>>>(fc0, fc1_w, fc1_b, fcA, BATCH, 512, 512, 1);
        fc64_kernel<<<grid1, 256>>>(fcA, fc2_w, fc2_b, fcB, BATCH, 512, 512, 1);
        dim3 grid3(1, BATCH / 64);
        fc64_kernel<<<grid3, 256>>>(fcB, fc3_w, fc3_b, (float*)d_out, BATCH, 10, 512, 0);
    }
}